// round 13
// baseline (speedup 1.0000x reference)
#include <cuda_runtime.h>
#include <cuda_bf16.h>
#include <math.h>
#include <stdint.h>

// Problem dims
#define CB   64      // batch
#define CL   40      // seq len
#define CT   39      // decoder steps (L-1)
#define CH   512     // hidden
#define CDF  2048    // feature dim
#define CE   512     // embedding dim
#define CV   20000   // vocab
#define G4   2048    // 4*H

typedef unsigned long long u64;

// ---------------- fp32 scratch ----------------
constexpr int OFF_X    = 0;                        // (unused now, kept for layout stability)
constexpr int OFF_GINF = OFF_X    + CB*CL*CH;
constexpr int OFF_GINB = OFF_GINF + CB*CL*G4;
constexpr int OFF_HF   = OFF_GINB + CB*CL*G4;
constexpr int OFF_HB   = OFF_HF   + CL*CB*CH;
constexpr int OFF_HD   = OFF_HB   + CL*CB*CH;     // hD layout [B][T][H] contiguous 2496x512
constexpr int OFF_CF   = OFF_HD   + CB*CT*CH;
constexpr int OFF_CB2  = OFF_CF   + CB*CH;
constexpr int OFF_CD   = OFF_CB2  + CB*CH;
constexpr int OFF_HZ   = OFF_CD   + CB*CH;
constexpr int OFF_CTX  = OFF_HZ   + CB*CH;
constexpr int OFF_DEMB = OFF_CTX  + CB*2*CH;      // (unused now)
constexpr int OFF_EMBW = OFF_DEMB + CT*CB*CE;
constexpr int OFF_CTXW = OFF_EMBW + CT*CB*G4;
constexpr int OFF_PART = OFF_CTXW + CB*G4;
constexpr int SCRATCH_TOTAL = OFF_PART + 4*CB*G4;
__device__ __align__(256) float g_scratch[SCRATCH_TOTAL];
__device__ __align__(512) unsigned g_flags[128];   // distributed barrier flags (zero-init)

// ---------------- bf16 hi/lo scratch (hi at off, lo at off + size) ----------------
constexpr long BO_WOUT  = 0;                               // 20096 x 512 (pad of 20000)
constexpr long BO_FW    = BO_WOUT  + 2L*20096*512;         // 512 x 2048
constexpr long BO_WIF   = BO_FW    + 2L*512*2048;          // 2048 x 512
constexpr long BO_WIB   = BO_WIF   + 2L*2048*512;
constexpr long BO_WID   = BO_WIB   + 2L*2048*512;          // 2048 x 512 (first E cols)
constexpr long BO_FEATS = BO_WID   + 2L*2048*512;          // 2560 x 2048
constexpr long BO_X     = BO_FEATS + 2L*2560*2048;         // 2560 x 512
constexpr long BO_DEMB  = BO_X     + 2L*2560*512;          // 2560 x 512 (pad of 2496)
constexpr long BO_HD    = BO_DEMB  + 2L*2560*512;          // 2560 x 512 (pad of 2496)
constexpr long BF_TOTAL = BO_HD    + 2L*2560*512;
__device__ __align__(256) __nv_bfloat16 g_bf[BF_TOTAL];

// ---------------- helpers ----------------
__device__ __forceinline__ void fma2(u64 &d, u64 a, u64 b) {
    asm("fma.rn.f32x2 %0, %1, %2, %0;" : "+l"(d) : "l"(a), "l"(b));
}
__device__ __forceinline__ float pairsum(u64 v) {
    float lo = __uint_as_float((unsigned)(v & 0xffffffffull));
    float hi = __uint_as_float((unsigned)(v >> 32));
    return lo + hi;
}
__device__ __forceinline__ void sts4(float* dst, float4 v) {
    *reinterpret_cast<float2*>(dst)     = make_float2(v.x, v.y);
    *reinterpret_cast<float2*>(dst + 2) = make_float2(v.z, v.w);
}
__device__ __forceinline__ uint32_t smem_u32(const void* p) {
    uint32_t a;
    asm("{ .reg .u64 t; cvta.to.shared.u64 t, %1; cvt.u32.u64 %0, t; }" : "=r"(a) : "l"(p));
    return a;
}
__device__ __forceinline__ void cp16(uint32_t dst, const void* src) {
    asm volatile("cp.async.cg.shared.global [%0], [%1], 16;" :: "r"(dst), "l"(src) : "memory");
}
__device__ __forceinline__ void cp_commit() {
    asm volatile("cp.async.commit_group;" ::: "memory");
}
__device__ __forceinline__ void cp_wait0() {
    asm volatile("cp.async.wait_group 0;" ::: "memory");
}
__device__ __forceinline__ void cp_wait1() {
    asm volatile("cp.async.wait_group 1;" ::: "memory");
}
__device__ __forceinline__ void ldsm4(uint32_t* r, uint32_t addr) {
    asm volatile("ldmatrix.sync.aligned.m8n8.x4.shared.b16 {%0,%1,%2,%3}, [%4];"
                 : "=r"(r[0]), "=r"(r[1]), "=r"(r[2]), "=r"(r[3]) : "r"(addr));
}
__device__ __forceinline__ void mma16816(float* d, const uint32_t* a, const uint32_t* b) {
    asm volatile("mma.sync.aligned.m16n8k16.row.col.f32.bf16.bf16.f32 "
                 "{%0,%1,%2,%3}, {%4,%5,%6,%7}, {%8,%9}, {%0,%1,%2,%3};"
                 : "+f"(d[0]), "+f"(d[1]), "+f"(d[2]), "+f"(d[3])
                 : "r"(a[0]), "r"(a[1]), "r"(a[2]), "r"(a[3]), "r"(b[0]), "r"(b[1]));
}
// swizzled element index for (row r, k-chunk c) in a [128][32] bf16 tile; 8 elems/chunk.
__device__ __forceinline__ int swzi(int r, int c) {
    int cc = (c + r + (r >> 2)) & 3;
    return r * 32 + cc * 8;
}
__device__ __forceinline__ void split1(float v, __nv_bfloat16& h, __nv_bfloat16& l) {
    h = __float2bfloat16(v);
    l = __float2bfloat16(v - __bfloat162float(h));
}

// ---------------- distributed-flag grid barrier (exactly 128 blocks) ----------------
// Each block owns one flag word; phases are monotone across kernel launches
// (each block resumes from its own flag), so no reset race exists.
__device__ __forceinline__ unsigned fbar_begin() {
    unsigned p;
    asm volatile("ld.volatile.global.u32 %0, [%1];" : "=r"(p) : "l"(&g_flags[blockIdx.x]));
    return p;
}
__device__ __forceinline__ void fbar(unsigned &phase) {
    phase += 1u;
    __syncthreads();
    if (threadIdx.x < 32) {
        if (threadIdx.x == 0) {
            __threadfence();    // release my writes
            asm volatile("st.volatile.global.u32 [%0], %1;"
                         :: "l"(&g_flags[blockIdx.x]), "r"(phase));
        }
        unsigned m;
        do {
            uint4 v;
            asm volatile("ld.volatile.global.v4.u32 {%0,%1,%2,%3}, [%4];"
                         : "=r"(v.x), "=r"(v.y), "=r"(v.z), "=r"(v.w)
                         : "l"(&g_flags[threadIdx.x * 4]));
            m = min(min(v.x, v.y), min(v.z, v.w));
#pragma unroll
            for (int o = 16; o > 0; o >>= 1)
                m = min(m, __shfl_xor_sync(0xffffffffu, m, o));
        } while (m < phase);
        __threadfence();        // acquire (invalidates L1 for fresh reads)
    }
    __syncthreads();
}

// ================= split fp32 -> bf16 hi/lo (with row padding to zeros) ============
__global__ void split_bf16(const float* __restrict__ src, int ld, int rows_valid, int cols,
                           __nv_bfloat16* __restrict__ hi, long losz, long total)
{
    long idx = (long)blockIdx.x * 256 + threadIdx.x;
    if (idx >= total) return;
    long r = idx / cols;
    int  c = (int)(idx - r * cols);
    float v = (r < rows_valid) ? src[r * (long)ld + c] : 0.f;
    __nv_bfloat16 h, l; split1(v, h, l);
    hi[idx]        = h;
    hi[idx + losz] = l;
}

// ================= HMMA GEMM (double-buffered): C = A * W^T (+b0+b1) ==============
// Optional bf16 hi/lo split output Csp (lo at +Csp_losz), same (row,col,ldc) indexing.
constexpr int MMA_STAGE_B = 32768;          // bytes per stage
constexpr int MMA_SMEM    = 2 * MMA_STAGE_B;

__global__ __launch_bounds__(256) void gemm_mma(
    const __nv_bfloat16* __restrict__ Ah, long Asz,
    const __nv_bfloat16* __restrict__ Wh, long Wsz,
    float* __restrict__ C, int ldc, int Mvalid, int N, int K,
    const float* __restrict__ bias0, const float* __restrict__ bias1,
    __nv_bfloat16* __restrict__ Csp, long Csp_losz)
{
    extern __shared__ __align__(128) __nv_bfloat16 dynsmem[];
    const uint32_t base = smem_u32(dynsmem);

    const int tid  = threadIdx.x;
    const int wid  = tid >> 5, lane = tid & 31;
    const int wm   = wid >> 2;          // 0..1  (64 rows each)
    const int wn   = wid & 3;           // 0..3  (32 cols each)
    const int m0   = blockIdx.x * 128, n0 = blockIdx.y * 128;

    const __nv_bfloat16* Al = Ah + Asz;
    const __nv_bfloat16* Wl = Wh + Wsz;

    float acc[4][4][4];
#pragma unroll
    for (int i = 0; i < 4; i++)
#pragma unroll
        for (int j = 0; j < 4; j++)
#pragma unroll
            for (int q = 0; q < 4; q++) acc[i][j][q] = 0.f;

    const int s_r0 = tid >> 2, s_c0 = tid & 3;
    const int s_r1 = (tid + 256) >> 2, s_c1 = tid & 3;
    const uint32_t so0 = (uint32_t)swzi(s_r0, s_c0) * 2;
    const uint32_t so1 = (uint32_t)swzi(s_r1, s_c1) * 2;

    const int a_r  = lane & 15;
    const int a_cg = lane >> 4;
    const int b_r  = (lane & 7) + ((lane >> 4) << 3);
    const int b_cg = (lane >> 3) & 1;

    const int nch = K >> 5;

    auto load_stage = [&](int c, uint32_t sb) {
        const int k0 = c << 5;
        long ga0 = (long)(m0 + s_r0) * K + k0 + s_c0 * 8;
        long gb0 = (long)(n0 + s_r0) * K + k0 + s_c0 * 8;
        cp16(sb +         so0, Ah + ga0);
        cp16(sb +  8192 + so0, Al + ga0);
        cp16(sb + 16384 + so0, Wh + gb0);
        cp16(sb + 24576 + so0, Wl + gb0);
        long ga1 = (long)(m0 + s_r1) * K + k0 + s_c1 * 8;
        long gb1 = (long)(n0 + s_r1) * K + k0 + s_c1 * 8;
        cp16(sb +         so1, Ah + ga1);
        cp16(sb +  8192 + so1, Al + ga1);
        cp16(sb + 16384 + so1, Wh + gb1);
        cp16(sb + 24576 + so1, Wl + gb1);
        cp_commit();
    };

    load_stage(0, base);

    for (int c = 0; c < nch; c++) {
        const uint32_t cb = base + (uint32_t)(c & 1) * MMA_STAGE_B;
        if (c + 1 < nch) {
            load_stage(c + 1, base + (uint32_t)((c + 1) & 1) * MMA_STAGE_B);
            cp_wait1();
        } else {
            cp_wait0();
        }
        __syncthreads();

        const uint32_t bAh = cb, bAl = cb + 8192, bWh = cb + 16384, bWl = cb + 24576;
#pragma unroll
        for (int h = 0; h < 2; h++) {
            uint32_t ah[4][4], al[4][4];
#pragma unroll
            for (int t = 0; t < 4; t++) {
                int r  = wm * 64 + t * 16 + a_r;
                int ch = 2 * h + a_cg;
                uint32_t off = (uint32_t)swzi(r, ch) * 2;
                ldsm4(ah[t], bAh + off);
                ldsm4(al[t], bAl + off);
            }
            uint32_t bh[4][2], bl[4][2];
#pragma unroll
            for (int p = 0; p < 2; p++) {
                int r  = wn * 32 + p * 16 + b_r;
                int ch = 2 * h + b_cg;
                uint32_t off = (uint32_t)swzi(r, ch) * 2;
                uint32_t tmp[4];
                ldsm4(tmp, bWh + off);
                bh[2*p][0] = tmp[0]; bh[2*p][1] = tmp[1];
                bh[2*p+1][0] = tmp[2]; bh[2*p+1][1] = tmp[3];
                ldsm4(tmp, bWl + off);
                bl[2*p][0] = tmp[0]; bl[2*p][1] = tmp[1];
                bl[2*p+1][0] = tmp[2]; bl[2*p+1][1] = tmp[3];
            }
#pragma unroll
            for (int t = 0; t < 4; t++)
#pragma unroll
                for (int n = 0; n < 4; n++) {
                    mma16816(acc[t][n], ah[t], bh[n]);
                    mma16816(acc[t][n], ah[t], bl[n]);
                    mma16816(acc[t][n], al[t], bh[n]);
                }
        }
        __syncthreads();
    }

    // ---- epilogue ----
#pragma unroll
    for (int t = 0; t < 4; t++) {
#pragma unroll
        for (int n = 0; n < 4; n++) {
            int row = m0 + wm * 64 + t * 16 + (lane >> 2);
            int col = n0 + wn * 32 + n * 8 + 2 * (lane & 3);
            if (col < N) {
                float bx = 0.f, by = 0.f;
                if (bias0) { bx += bias0[col]; by += bias0[col + 1]; }
                if (bias1) { bx += bias1[col]; by += bias1[col + 1]; }
#pragma unroll
                for (int half = 0; half < 2; half++) {
                    int r = row + 8 * half;
                    if (r < Mvalid) {
                        float vx = acc[t][n][2*half]     + bx;
                        float vy = acc[t][n][2*half + 1] + by;
                        if (C)
                            *reinterpret_cast<float2*>(C + (long)r * ldc + col) =
                                make_float2(vx, vy);
                        if (Csp) {
                            __nv_bfloat16 hx, lx, hy, ly;
                            split1(vx, hx, lx); split1(vy, hy, ly);
                            long o = (long)r * ldc + col;
                            Csp[o] = hx; Csp[o + 1] = hy;
                            Csp[o + Csp_losz] = lx; Csp[o + Csp_losz + 1] = ly;
                        }
                    }
                }
            }
        }
    }
}

// ---------------- small-M GEMM (used once for ctx @ Wih_d[:,E:]) ----------------
__global__ __launch_bounds__(256) void gemm_small64(
    const float* __restrict__ A, int lda,
    const float* __restrict__ W, int ldw,
    float* __restrict__ P, int N, int Kps)
{
    __shared__ float As[64][34];
    __shared__ float Ws[32][34];
    const int tid  = threadIdx.x;
    const int n0   = blockIdx.x * 32;
    const int kb   = blockIdx.y * Kps;
    const int tm   = tid >> 4;
    const int tn   = tid & 15;
    const int lrow = tid >> 3;
    const int lcol = (tid & 7) << 2;

    u64 acc[4][2];
#pragma unroll
    for (int i = 0; i < 4; i++) { acc[i][0] = 0ull; acc[i][1] = 0ull; }

    const int nk = Kps >> 5;
    float4 pa0, pa1, pw;
    {
        int k = kb + lcol;
        pa0 = *reinterpret_cast<const float4*>(A + (long)lrow * lda + k);
        pa1 = *reinterpret_cast<const float4*>(A + (long)(lrow + 32) * lda + k);
        pw  = *reinterpret_cast<const float4*>(W + (long)(n0 + lrow) * ldw + k);
    }
    for (int c = 0; c < nk; c++) {
        sts4(&As[lrow][lcol],      pa0);
        sts4(&As[lrow + 32][lcol], pa1);
        sts4(&Ws[lrow][lcol],      pw);
        __syncthreads();
        if (c + 1 < nk) {
            int k = kb + ((c + 1) << 5) + lcol;
            pa0 = *reinterpret_cast<const float4*>(A + (long)lrow * lda + k);
            pa1 = *reinterpret_cast<const float4*>(A + (long)(lrow + 32) * lda + k);
            pw  = *reinterpret_cast<const float4*>(W + (long)(n0 + lrow) * ldw + k);
        }
#pragma unroll
        for (int kk = 0; kk < 16; kk++) {
            u64 a2[4], w2[2];
#pragma unroll
            for (int i = 0; i < 4; i++)
                a2[i] = *reinterpret_cast<const u64*>(&As[tm + 16 * i][kk << 1]);
#pragma unroll
            for (int j = 0; j < 2; j++)
                w2[j] = *reinterpret_cast<const u64*>(&Ws[tn + 16 * j][kk << 1]);
#pragma unroll
            for (int i = 0; i < 4; i++)
#pragma unroll
                for (int j = 0; j < 2; j++) fma2(acc[i][j], a2[i], w2[j]);
        }
        __syncthreads();
    }
    float* out = P + (long)blockIdx.y * 64 * N;
#pragma unroll
    for (int i = 0; i < 4; i++)
#pragma unroll
        for (int j = 0; j < 2; j++)
            out[(tm + 16 * i) * (long)N + n0 + tn + 16 * j] = pairsum(acc[i][j]);
}

// ---------------- persistent LSTM machinery ----------------
__device__ __forceinline__ void step_gemm(const float* __restrict__ A, int lda,
                                          const float* __restrict__ W,
                                          float* __restrict__ part, int bx)
{
    __shared__ float As[64][34];
    __shared__ float Ws[32][34];
    const int tid  = threadIdx.x;
    const int n0   = (bx & 63) * 32;
    const int kb   = (bx >> 6) * 256;
    const int tm   = tid >> 4;
    const int tn   = tid & 15;
    const int lrow = tid >> 3;
    const int lcol = (tid & 7) << 2;

    u64 acc[4][2];
#pragma unroll
    for (int i = 0; i < 4; i++) { acc[i][0] = 0ull; acc[i][1] = 0ull; }

    float4 pa0, pa1, pw;
    {
        int k = kb + lcol;
        pa0 = *reinterpret_cast<const float4*>(A + (long)lrow * lda + k);
        pa1 = *reinterpret_cast<const float4*>(A + (long)(lrow + 32) * lda + k);
        pw  = *reinterpret_cast<const float4*>(W + (long)(n0 + lrow) * CH + k);
    }
    for (int c = 0; c < 8; c++) {
        sts4(&As[lrow][lcol],      pa0);
        sts4(&As[lrow + 32][lcol], pa1);
        sts4(&Ws[lrow][lcol],      pw);
        __syncthreads();
        if (c < 7) {
            int k = kb + ((c + 1) << 5) + lcol;
            pa0 = *reinterpret_cast<const float4*>(A + (long)lrow * lda + k);
            pa1 = *reinterpret_cast<const float4*>(A + (long)(lrow + 32) * lda + k);
            pw  = *reinterpret_cast<const float4*>(W + (long)(n0 + lrow) * CH + k);
        }
#pragma unroll
        for (int kk = 0; kk < 16; kk++) {
            u64 a2[4], w2[2];
#pragma unroll
            for (int i = 0; i < 4; i++)
                a2[i] = *reinterpret_cast<const u64*>(&As[tm + 16 * i][kk << 1]);
#pragma unroll
            for (int j = 0; j < 2; j++)
                w2[j] = *reinterpret_cast<const u64*>(&Ws[tn + 16 * j][kk << 1]);
#pragma unroll
            for (int i = 0; i < 4; i++)
#pragma unroll
                for (int j = 0; j < 2; j++) fma2(acc[i][j], a2[i], w2[j]);
        }
        __syncthreads();
    }
    float* out = part + (long)(bx >> 6) * 64 * G4;
#pragma unroll
    for (int i = 0; i < 4; i++)
#pragma unroll
        for (int j = 0; j < 2; j++)
            out[(tm + 16 * i) * G4 + n0 + tn + 16 * j] = pairsum(acc[i][j]);
}

__device__ __forceinline__ void gates_fn(const float* P, const float* D1, int ldd1,
                                         const float* D2, float* c,
                                         float* h_out, int h_ld, int idx,
                                         __nv_bfloat16* hs, long hs_losz)
{
    int b = idx >> 9, u = idx & 511;
    const float* g0 = P + (long)b * G4;
    const float* g1 = P + (long)CB * G4 + (long)b * G4;
    const float* d1 = D1 + (long)b * ldd1;
    float gi = g0[u]        + g1[u]        + d1[u];
    float gf = g0[512 + u]  + g1[512 + u]  + d1[512 + u];
    float gg = g0[1024 + u] + g1[1024 + u] + d1[1024 + u];
    float go = g0[1536 + u] + g1[1536 + u] + d1[1536 + u];
    if (D2) {
        const float* d2 = D2 + (long)b * G4;
        gi += d2[u]; gf += d2[512 + u]; gg += d2[1024 + u]; go += d2[1536 + u];
    }
    float i_ = 1.f / (1.f + expf(-gi));
    float f_ = 1.f / (1.f + expf(-gf));
    float g_ = tanhf(gg);
    float o_ = 1.f / (1.f + expf(-go));
    float cn = f_ * c[idx] + i_ * g_;
    c[idx] = cn;
    float hv = o_ * tanhf(cn);
    long lin = (long)b * h_ld + u;
    h_out[lin] = hv;
    if (hs) {
        __nv_bfloat16 hh, hl; split1(hv, hh, hl);
        hs[lin] = hh;
        hs[lin + hs_losz] = hl;
    }
}

// ---- fused fwd+bwd encoder LSTMs: interleaved phases, ONE barrier per phase ----
__global__ __launch_bounds__(256) void enc_lstm2(
    const float* __restrict__ Whh_f, const float* __restrict__ Whh_b,
    const float* __restrict__ ginF,  const float* __restrict__ ginB,
    float* __restrict__ hF, float* __restrict__ hB,
    float* __restrict__ cF, float* __restrict__ cB2,
    const float* __restrict__ hz,
    float* __restrict__ partF, float* __restrict__ partB)
{
    unsigned phase = fbar_begin();
    const int bx  = blockIdx.x;
    const int idx = bx * 256 + threadIdx.x;
    for (int p = 0; p < 2 * CL; p++) {
        const int li = p & 1;            // 0 = fwd, 1 = bwd
        const int s  = p >> 1;
        const float* Whh  = li ? Whh_b : Whh_f;
        const float* gin  = li ? ginB  : ginF;
        float* hbase = li ? hB : hF;
        float* cc    = li ? cB2 : cF;
        float* part  = li ? partB : partF;
        const int l = li ? (CL - 1 - s) : s;
        const float* hin;
        if (s == 0) hin = hz;
        else {
            int lp = li ? (l + 1) : (l - 1);
            hin = hbase + (long)lp * CB * CH;
        }
        step_gemm(hin, CH, Whh, part, bx);
        fbar(phase);                      // part(li,s) complete across all blocks
        gates_fn(part, gin + (long)l * G4, CL * G4, nullptr, cc,
                 hbase + (long)l * CB * CH, CH, idx, nullptr, 0);
        // h(li,s) is consumed by gemm(li,s+1) two phases later -> guarded by next fbar
    }
}

// ---- decoder persistent LSTM (2 barriers per step; writes bf16 split of h) ----
__global__ __launch_bounds__(256) void lstm_persist(
    const float* __restrict__ Whh,
    const float* __restrict__ gin, long gin_step, int gin_ld,
    const float* __restrict__ D2,
    const float* __restrict__ hz,
    float* __restrict__ hbase, long h_step, int h_ld,
    float* __restrict__ c, float* __restrict__ part,
    int nsteps,
    __nv_bfloat16* __restrict__ hs, long hs_losz)
{
    unsigned phase = fbar_begin();
    const int bx  = blockIdx.x;
    const int idx = bx * 256 + threadIdx.x;
    for (int s = 0; s < nsteps; s++) {
        const float* hin = (s == 0) ? hz : hbase + (long)(s - 1) * h_step;
        int hlda = (s == 0) ? CH : h_ld;
        step_gemm(hin, hlda, Whh, part, bx);
        fbar(phase);
        gates_fn(part, gin + (long)s * gin_step, gin_ld, D2, c,
                 hbase + (long)s * h_step, h_ld, idx,
                 hs ? hs + (long)s * h_step : nullptr, hs_losz);
        if (s + 1 < nsteps) fbar(phase);  // h(s) visible before gemm(s+1)
    }
}

// ---------------- small elementwise kernels ----------------
__global__ void zero_state(float* cF, float* cB, float* cD, float* hz)
{
    int idx = blockIdx.x * blockDim.x + threadIdx.x;
    cF[idx] = 0.f; cB[idx] = 0.f; cD[idx] = 0.f; hz[idx] = 0.f;
}

// zero pad rows (2496..2559) of DEMB and HD splits (hi and lo)
__global__ void zero_bf_pads(__nv_bfloat16* base)
{
    int i = blockIdx.x * 256 + threadIdx.x;   // 0..32767 = 64*512
    long r = 2496L * 512 + i;
    base[BO_DEMB + r] = __float2bfloat16(0.f);
    base[BO_DEMB + 2560L * 512 + r] = __float2bfloat16(0.f);
    base[BO_HD + r] = __float2bfloat16(0.f);
    base[BO_HD + 2560L * 512 + r] = __float2bfloat16(0.f);
}

__global__ void ctx_sum(const float* __restrict__ hF, const float* __restrict__ hB,
                        float* __restrict__ ctx)
{
    int idx = blockIdx.x * blockDim.x + threadIdx.x;  // 64*1024
    int b = idx >> 10, j = idx & 1023;
    float s = 0.f;
    if (j < 512) {
        for (int l = 0; l < CL; l++) s += hF[((long)l * CB + b) * CH + j];
    } else {
        int j2 = j - 512;
        for (int l = 0; l < CL; l++) s += hB[((long)l * CB + b) * CH + j2];
    }
    ctx[idx] = s;
}

__global__ void ctx_combine(const float* __restrict__ P,
                            const float* __restrict__ b0,
                            const float* __restrict__ b1,
                            float* __restrict__ ctxW)
{
    int idx = blockIdx.x * blockDim.x + threadIdx.x;  // 64*2048
    int b = idx >> 11, n = idx & 2047;
    float s = b0[n] + b1[n];
#pragma unroll
    for (int z = 0; z < 4; z++) s += P[((long)z * CB + b) * G4 + n];
    ctxW[idx] = s;
}

// embedding gather writing bf16 hi/lo split directly
__global__ void gather_emb_split(const float* __restrict__ emb, const int* __restrict__ targets,
                                 __nv_bfloat16* __restrict__ dst, long losz)
{
    int idx = blockIdx.x * blockDim.x + threadIdx.x;  // 39*64*512
    int e = idx & 511;
    int r = idx >> 9;
    int t = r / CB, b = r - t * CB;
    int tgt = targets[b * CL + t];
    float v = emb[(long)tgt * CE + e];
    __nv_bfloat16 h, l; split1(v, h, l);
    dst[idx] = h;
    dst[idx + losz] = l;
}

// ---------------- launch ----------------
static inline int sgrid(long n) { return (int)((n + 255) / 256); }

extern "C" void kernel_launch(void* const* d_in, const int* in_sizes, int n_in,
                              void* d_out, int out_size)
{
    (void)in_sizes; (void)n_in; (void)out_size;
    const float* feats  = (const float*)d_in[0];
    const float* feat_W = (const float*)d_in[1];
    const float* feat_b = (const float*)d_in[2];
    const float* Wih_f  = (const float*)d_in[3];
    const float* Whh_f  = (const float*)d_in[4];
    const float* bih_f  = (const float*)d_in[5];
    const float* bhh_f  = (const float*)d_in[6];
    const float* Wih_b  = (const float*)d_in[7];
    const float* Whh_b  = (const float*)d_in[8];
    const float* bih_b  = (const float*)d_in[9];
    const float* bhh_b  = (const float*)d_in[10];
    const float* emb    = (const float*)d_in[11];
    const float* Wih_d  = (const float*)d_in[12];
    const float* Whh_d  = (const float*)d_in[13];
    const float* bih_d  = (const float*)d_in[14];
    const float* bhh_d  = (const float*)d_in[15];
    // d_in[16..20]: attention params — provably unused (softmax over singleton axis -> ones)
    const float* out_W  = (const float*)d_in[21];
    const float* out_b  = (const float*)d_in[22];
    const int*   targets = (const int*)d_in[23];
    float* out = (float*)d_out;

    float* S = nullptr;
    cudaGetSymbolAddress((void**)&S, g_scratch);
    __nv_bfloat16* BF = nullptr;
    cudaGetSymbolAddress((void**)&BF, g_bf);

    float* ginF  = S + OFF_GINF;
    float* ginB  = S + OFF_GINB;
    float* hF    = S + OFF_HF;
    float* hB    = S + OFF_HB;
    float* hD    = S + OFF_HD;
    float* cF    = S + OFF_CF;
    float* cBb   = S + OFF_CB2;
    float* cD    = S + OFF_CD;
    float* hz    = S + OFF_HZ;
    float* ctx   = S + OFF_CTX;
    float* embW  = S + OFF_EMBW;
    float* ctxW  = S + OFF_CTXW;
    float* part  = S + OFF_PART;                    // partF = part, partB = part + 2*CB*G4
    float* partB = part + 2L * CB * G4;

    cudaFuncSetAttribute(gemm_mma, cudaFuncAttributeMaxDynamicSharedMemorySize, MMA_SMEM);

    zero_state<<<128, 256>>>(cF, cBb, cD, hz);
    zero_bf_pads<<<128, 256>>>(BF);

    // ---- weight/input splits to bf16 hi/lo ----
    split_bf16<<<sgrid(20096L*512), 256>>>(out_W, 512, 20000, 512,
                                           BF + BO_WOUT, 20096L*512, 20096L*512);
    split_bf16<<<sgrid(512L*2048), 256>>>(feat_W, 2048, 512, 2048,
                                          BF + BO_FW, 512L*2048, 512L*2048);
    split_bf16<<<sgrid(2048L*512), 256>>>(Wih_f, 512, 2048, 512,
                                          BF + BO_WIF, 2048L*512, 2048L*512);
    split_bf16<<<sgrid(2048L*512), 256>>>(Wih_b, 512, 2048, 512,
                                          BF + BO_WIB, 2048L*512, 2048L*512);
    split_bf16<<<sgrid(2048L*512), 256>>>(Wih_d, 2*CH + CE, 2048, 512,
                                          BF + BO_WID, 2048L*512, 2048L*512);
    split_bf16<<<sgrid(2560L*2048), 256>>>(feats, 2048, 2560, 2048,
                                           BF + BO_FEATS, 2560L*2048, 2560L*2048);

    // x = feats @ feat_W^T + feat_b  -> written DIRECTLY as bf16 hi/lo split (fp32 x unused)
    gemm_mma<<<dim3(20, 4), 256, MMA_SMEM>>>(BF + BO_FEATS, 2560L*2048, BF + BO_FW, 512L*2048,
                                             nullptr, CH, 2560, CH, CDF, feat_b, nullptr,
                                             BF + BO_X, 2560L*512);

    // encoder input-gate precompute
    gemm_mma<<<dim3(20, 16), 256, MMA_SMEM>>>(BF + BO_X, 2560L*512, BF + BO_WIF, 2048L*512,
                                              ginF, G4, 2560, G4, CH, bih_f, bhh_f, nullptr, 0);
    gemm_mma<<<dim3(20, 16), 256, MMA_SMEM>>>(BF + BO_X, 2560L*512, BF + BO_WIB, 2048L*512,
                                              ginB, G4, 2560, G4, CH, bih_b, bhh_b, nullptr, 0);

    // fused fwd+bwd encoder LSTMs (interleaved phases, 1 barrier per phase)
    enc_lstm2<<<128, 256>>>(Whh_f, Whh_b, ginF, ginB, hF, hB, cF, cBb, hz, part, partB);

    // ctx[b] = sum_l enc[b,l,:]  (attention collapses: softmax over singleton axis)
    ctx_sum<<<256, 256>>>(hF, hB, ctx);

    // decoder input-gate precompute (gather writes bf16 split directly)
    gather_emb_split<<<(CT * CB * CE) / 256, 256>>>(emb, targets, BF + BO_DEMB, 2560L*512);
    gemm_mma<<<dim3(20, 16), 256, MMA_SMEM>>>(BF + BO_DEMB, 2560L*512, BF + BO_WID, 2048L*512,
                                              embW, G4, 2496, G4, CE, nullptr, nullptr,
                                              nullptr, 0);
    gemm_small64<<<dim3(64, 4), 256>>>(ctx, 2 * CH, Wih_d + CE, 2 * CH + CE, part, G4, 256);
    ctx_combine<<<512, 256>>>(part, bih_d, bhh_d, ctxW);

    // decoder LSTM persistent (hD layout [B][T][H]; gates also write bf16 split of hD)
    lstm_persist<<<128, 256>>>(Whh_d, embW, (long)CB * G4, G4, ctxW, hz,
                               hD, (long)CH, CT * CH, cD, part, CT,
                               BF + BO_HD, 2560L*512);

    // output projection: out[b,t,:] = hD[b,t,:] @ out_W^T + out_b  (HMMA)
    gemm_mma<<<dim3(20, 157), 256, MMA_SMEM>>>(BF + BO_HD, 2560L*512, BF + BO_WOUT, 20096L*512,
                                               out, CV, 2496, CV, CH, out_b, nullptr,
                                               nullptr, 0);
}

// round 14
// speedup vs baseline: 1.4154x; 1.4154x over previous
#include <cuda_runtime.h>
#include <cuda_bf16.h>
#include <math.h>
#include <stdint.h>

// Problem dims
#define CB   64      // batch
#define CL   40      // seq len
#define CT   39      // decoder steps (L-1)
#define CH   512     // hidden
#define CDF  2048    // feature dim
#define CE   512     // embedding dim
#define CV   20000   // vocab
#define G4   2048    // 4*H

typedef unsigned long long u64;

// ---------------- fp32 scratch ----------------
constexpr int OFF_X    = 0;                        // (unused; layout stability)
constexpr int OFF_GINF = OFF_X    + CB*CL*CH;
constexpr int OFF_GINB = OFF_GINF + CB*CL*G4;
constexpr int OFF_HF   = OFF_GINB + CB*CL*G4;
constexpr int OFF_HB   = OFF_HF   + CL*CB*CH;
constexpr int OFF_HD   = OFF_HB   + CL*CB*CH;     // hD layout [B][T][H] contiguous 2496x512
constexpr int OFF_CF   = OFF_HD   + CB*CT*CH;
constexpr int OFF_CB2  = OFF_CF   + CB*CH;
constexpr int OFF_CD   = OFF_CB2  + CB*CH;
constexpr int OFF_HZ   = OFF_CD   + CB*CH;
constexpr int OFF_CTX  = OFF_HZ   + CB*CH;
constexpr int OFF_DEMB = OFF_CTX  + CB*2*CH;      // (unused)
constexpr int OFF_EMBW = OFF_DEMB + CT*CB*CE;
constexpr int OFF_CTXW = OFF_EMBW + CT*CB*G4;
constexpr int OFF_PART = OFF_CTXW + CB*G4;
constexpr int SCRATCH_TOTAL = OFF_PART + 4*CB*G4;
__device__ __align__(256) float g_scratch[SCRATCH_TOTAL];
__device__ unsigned g_bar = 0;   // atomic barrier counter (always 0 between launches)

// ---------------- bf16 hi/lo scratch (hi at off, lo at off + size) ----------------
constexpr long BO_WOUT  = 0;                               // 20096 x 512 (pad of 20000)
constexpr long BO_FW    = BO_WOUT  + 2L*20096*512;         // 512 x 2048
constexpr long BO_WIF   = BO_FW    + 2L*512*2048;          // 2048 x 512
constexpr long BO_WIB   = BO_WIF   + 2L*2048*512;
constexpr long BO_WID   = BO_WIB   + 2L*2048*512;          // 2048 x 512 (first E cols)
constexpr long BO_FEATS = BO_WID   + 2L*2048*512;          // 2560 x 2048
constexpr long BO_X     = BO_FEATS + 2L*2560*2048;         // 2560 x 512
constexpr long BO_DEMB  = BO_X     + 2L*2560*512;          // 2560 x 512 (pad of 2496)
constexpr long BO_HD    = BO_DEMB  + 2L*2560*512;          // 2560 x 512 (pad of 2496)
constexpr long BF_TOTAL = BO_HD    + 2L*2560*512;
__device__ __align__(256) __nv_bfloat16 g_bf[BF_TOTAL];

// ---------------- helpers ----------------
__device__ __forceinline__ void fma2(u64 &d, u64 a, u64 b) {
    asm("fma.rn.f32x2 %0, %1, %2, %0;" : "+l"(d) : "l"(a), "l"(b));
}
__device__ __forceinline__ float pairsum(u64 v) {
    float lo = __uint_as_float((unsigned)(v & 0xffffffffull));
    float hi = __uint_as_float((unsigned)(v >> 32));
    return lo + hi;
}
__device__ __forceinline__ void sts4(float* dst, float4 v) {
    *reinterpret_cast<float2*>(dst)     = make_float2(v.x, v.y);
    *reinterpret_cast<float2*>(dst + 2) = make_float2(v.z, v.w);
}
__device__ __forceinline__ uint32_t smem_u32(const void* p) {
    uint32_t a;
    asm("{ .reg .u64 t; cvta.to.shared.u64 t, %1; cvt.u32.u64 %0, t; }" : "=r"(a) : "l"(p));
    return a;
}
__device__ __forceinline__ void cp16(uint32_t dst, const void* src) {
    asm volatile("cp.async.cg.shared.global [%0], [%1], 16;" :: "r"(dst), "l"(src) : "memory");
}
__device__ __forceinline__ void cp_commit() {
    asm volatile("cp.async.commit_group;" ::: "memory");
}
__device__ __forceinline__ void cp_wait0() {
    asm volatile("cp.async.wait_group 0;" ::: "memory");
}
__device__ __forceinline__ void cp_wait1() {
    asm volatile("cp.async.wait_group 1;" ::: "memory");
}
__device__ __forceinline__ void ldsm4(uint32_t* r, uint32_t addr) {
    asm volatile("ldmatrix.sync.aligned.m8n8.x4.shared.b16 {%0,%1,%2,%3}, [%4];"
                 : "=r"(r[0]), "=r"(r[1]), "=r"(r[2]), "=r"(r[3]) : "r"(addr));
}
__device__ __forceinline__ void mma16816(float* d, const uint32_t* a, const uint32_t* b) {
    asm volatile("mma.sync.aligned.m16n8k16.row.col.f32.bf16.bf16.f32 "
                 "{%0,%1,%2,%3}, {%4,%5,%6,%7}, {%8,%9}, {%0,%1,%2,%3};"
                 : "+f"(d[0]), "+f"(d[1]), "+f"(d[2]), "+f"(d[3])
                 : "r"(a[0]), "r"(a[1]), "r"(a[2]), "r"(a[3]), "r"(b[0]), "r"(b[1]));
}
// swizzled element index for (row r, k-chunk c) in a [128][32] bf16 tile; 8 elems/chunk.
__device__ __forceinline__ int swzi(int r, int c) {
    int cc = (c + r + (r >> 2)) & 3;
    return r * 32 + cc * 8;
}
__device__ __forceinline__ void split1(float v, __nv_bfloat16& h, __nv_bfloat16& l) {
    h = __float2bfloat16(v);
    l = __float2bfloat16(v - __bfloat162float(h));
}

// ---------------- atomic-counter grid barrier (128 resident blocks; R11-proven) ----
__device__ __forceinline__ void grid_bar(unsigned &target) {
    __syncthreads();
    target += 128u;
    if (threadIdx.x == 0) {
        __threadfence();                       // release
        atomicAdd(&g_bar, 1u);
        unsigned v;
        do {
            asm volatile("ld.volatile.global.u32 %0, [%1];" : "=r"(v) : "l"(&g_bar));
        } while (v < target);
        __threadfence();                       // acquire
    }
    __syncthreads();
}
__device__ __forceinline__ void grid_bar_final(unsigned target) {
    __syncthreads();
    if (threadIdx.x == 0) {
        __threadfence();
        unsigned old = atomicAdd(&g_bar, 1u);
        if (old == target + 127u) {            // last arriver resets for next launch
            __threadfence();
            asm volatile("st.volatile.global.u32 [%0], %1;" :: "l"(&g_bar), "r"(0u));
        }
    }
}

// ================= split fp32 -> bf16 hi/lo (with row padding to zeros) ============
__global__ void split_bf16(const float* __restrict__ src, int ld, int rows_valid, int cols,
                           __nv_bfloat16* __restrict__ hi, long losz, long total)
{
    long idx = (long)blockIdx.x * 256 + threadIdx.x;
    if (idx >= total) return;
    long r = idx / cols;
    int  c = (int)(idx - r * cols);
    float v = (r < rows_valid) ? src[r * (long)ld + c] : 0.f;
    __nv_bfloat16 h, l; split1(v, h, l);
    hi[idx]        = h;
    hi[idx + losz] = l;
}

// ================= HMMA GEMM (double-buffered): C = A * W^T (+b0+b1) ==============
// Optional bf16 hi/lo split output Csp (lo at +Csp_losz), same (row,col,ldc) indexing.
constexpr int MMA_STAGE_B = 32768;          // bytes per stage
constexpr int MMA_SMEM    = 2 * MMA_STAGE_B;

__global__ __launch_bounds__(256) void gemm_mma(
    const __nv_bfloat16* __restrict__ Ah, long Asz,
    const __nv_bfloat16* __restrict__ Wh, long Wsz,
    float* __restrict__ C, int ldc, int Mvalid, int N, int K,
    const float* __restrict__ bias0, const float* __restrict__ bias1,
    __nv_bfloat16* __restrict__ Csp, long Csp_losz)
{
    extern __shared__ __align__(128) __nv_bfloat16 dynsmem[];
    const uint32_t base = smem_u32(dynsmem);

    const int tid  = threadIdx.x;
    const int wid  = tid >> 5, lane = tid & 31;
    const int wm   = wid >> 2;          // 0..1  (64 rows each)
    const int wn   = wid & 3;           // 0..3  (32 cols each)
    const int m0   = blockIdx.x * 128, n0 = blockIdx.y * 128;

    const __nv_bfloat16* Al = Ah + Asz;
    const __nv_bfloat16* Wl = Wh + Wsz;

    float acc[4][4][4];
#pragma unroll
    for (int i = 0; i < 4; i++)
#pragma unroll
        for (int j = 0; j < 4; j++)
#pragma unroll
            for (int q = 0; q < 4; q++) acc[i][j][q] = 0.f;

    const int s_r0 = tid >> 2, s_c0 = tid & 3;
    const int s_r1 = (tid + 256) >> 2, s_c1 = tid & 3;
    const uint32_t so0 = (uint32_t)swzi(s_r0, s_c0) * 2;
    const uint32_t so1 = (uint32_t)swzi(s_r1, s_c1) * 2;

    const int a_r  = lane & 15;
    const int a_cg = lane >> 4;
    const int b_r  = (lane & 7) + ((lane >> 4) << 3);
    const int b_cg = (lane >> 3) & 1;

    const int nch = K >> 5;

    auto load_stage = [&](int c, uint32_t sb) {
        const int k0 = c << 5;
        long ga0 = (long)(m0 + s_r0) * K + k0 + s_c0 * 8;
        long gb0 = (long)(n0 + s_r0) * K + k0 + s_c0 * 8;
        cp16(sb +         so0, Ah + ga0);
        cp16(sb +  8192 + so0, Al + ga0);
        cp16(sb + 16384 + so0, Wh + gb0);
        cp16(sb + 24576 + so0, Wl + gb0);
        long ga1 = (long)(m0 + s_r1) * K + k0 + s_c1 * 8;
        long gb1 = (long)(n0 + s_r1) * K + k0 + s_c1 * 8;
        cp16(sb +         so1, Ah + ga1);
        cp16(sb +  8192 + so1, Al + ga1);
        cp16(sb + 16384 + so1, Wh + gb1);
        cp16(sb + 24576 + so1, Wl + gb1);
        cp_commit();
    };

    load_stage(0, base);

    for (int c = 0; c < nch; c++) {
        const uint32_t cb = base + (uint32_t)(c & 1) * MMA_STAGE_B;
        if (c + 1 < nch) {
            load_stage(c + 1, base + (uint32_t)((c + 1) & 1) * MMA_STAGE_B);
            cp_wait1();
        } else {
            cp_wait0();
        }
        __syncthreads();

        const uint32_t bAh = cb, bAl = cb + 8192, bWh = cb + 16384, bWl = cb + 24576;
#pragma unroll
        for (int h = 0; h < 2; h++) {
            uint32_t ah[4][4], al[4][4];
#pragma unroll
            for (int t = 0; t < 4; t++) {
                int r  = wm * 64 + t * 16 + a_r;
                int ch = 2 * h + a_cg;
                uint32_t off = (uint32_t)swzi(r, ch) * 2;
                ldsm4(ah[t], bAh + off);
                ldsm4(al[t], bAl + off);
            }
            uint32_t bh[4][2], bl[4][2];
#pragma unroll
            for (int p = 0; p < 2; p++) {
                int r  = wn * 32 + p * 16 + b_r;
                int ch = 2 * h + b_cg;
                uint32_t off = (uint32_t)swzi(r, ch) * 2;
                uint32_t tmp[4];
                ldsm4(tmp, bWh + off);
                bh[2*p][0] = tmp[0]; bh[2*p][1] = tmp[1];
                bh[2*p+1][0] = tmp[2]; bh[2*p+1][1] = tmp[3];
                ldsm4(tmp, bWl + off);
                bl[2*p][0] = tmp[0]; bl[2*p][1] = tmp[1];
                bl[2*p+1][0] = tmp[2]; bl[2*p+1][1] = tmp[3];
            }
#pragma unroll
            for (int t = 0; t < 4; t++)
#pragma unroll
                for (int n = 0; n < 4; n++) {
                    mma16816(acc[t][n], ah[t], bh[n]);
                    mma16816(acc[t][n], ah[t], bl[n]);
                    mma16816(acc[t][n], al[t], bh[n]);
                }
        }
        __syncthreads();
    }

    // ---- epilogue ----
#pragma unroll
    for (int t = 0; t < 4; t++) {
#pragma unroll
        for (int n = 0; n < 4; n++) {
            int row = m0 + wm * 64 + t * 16 + (lane >> 2);
            int col = n0 + wn * 32 + n * 8 + 2 * (lane & 3);
            if (col < N) {
                float bx = 0.f, by = 0.f;
                if (bias0) { bx += bias0[col]; by += bias0[col + 1]; }
                if (bias1) { bx += bias1[col]; by += bias1[col + 1]; }
#pragma unroll
                for (int half = 0; half < 2; half++) {
                    int r = row + 8 * half;
                    if (r < Mvalid) {
                        float vx = acc[t][n][2*half]     + bx;
                        float vy = acc[t][n][2*half + 1] + by;
                        if (C)
                            *reinterpret_cast<float2*>(C + (long)r * ldc + col) =
                                make_float2(vx, vy);
                        if (Csp) {
                            __nv_bfloat16 hx, lx, hy, ly;
                            split1(vx, hx, lx); split1(vy, hy, ly);
                            long o = (long)r * ldc + col;
                            Csp[o] = hx; Csp[o + 1] = hy;
                            Csp[o + Csp_losz] = lx; Csp[o + Csp_losz + 1] = ly;
                        }
                    }
                }
            }
        }
    }
}

// ---------------- small-M GEMM (used once for ctx @ Wih_d[:,E:]) ----------------
__global__ __launch_bounds__(256) void gemm_small64(
    const float* __restrict__ A, int lda,
    const float* __restrict__ W, int ldw,
    float* __restrict__ P, int N, int Kps)
{
    __shared__ float As[64][34];
    __shared__ float Ws[32][34];
    const int tid  = threadIdx.x;
    const int n0   = blockIdx.x * 32;
    const int kb   = blockIdx.y * Kps;
    const int tm   = tid >> 4;
    const int tn   = tid & 15;
    const int lrow = tid >> 3;
    const int lcol = (tid & 7) << 2;

    u64 acc[4][2];
#pragma unroll
    for (int i = 0; i < 4; i++) { acc[i][0] = 0ull; acc[i][1] = 0ull; }

    const int nk = Kps >> 5;
    float4 pa0, pa1, pw;
    {
        int k = kb + lcol;
        pa0 = *reinterpret_cast<const float4*>(A + (long)lrow * lda + k);
        pa1 = *reinterpret_cast<const float4*>(A + (long)(lrow + 32) * lda + k);
        pw  = *reinterpret_cast<const float4*>(W + (long)(n0 + lrow) * ldw + k);
    }
    for (int c = 0; c < nk; c++) {
        sts4(&As[lrow][lcol],      pa0);
        sts4(&As[lrow + 32][lcol], pa1);
        sts4(&Ws[lrow][lcol],      pw);
        __syncthreads();
        if (c + 1 < nk) {
            int k = kb + ((c + 1) << 5) + lcol;
            pa0 = *reinterpret_cast<const float4*>(A + (long)lrow * lda + k);
            pa1 = *reinterpret_cast<const float4*>(A + (long)(lrow + 32) * lda + k);
            pw  = *reinterpret_cast<const float4*>(W + (long)(n0 + lrow) * ldw + k);
        }
#pragma unroll
        for (int kk = 0; kk < 16; kk++) {
            u64 a2[4], w2[2];
#pragma unroll
            for (int i = 0; i < 4; i++)
                a2[i] = *reinterpret_cast<const u64*>(&As[tm + 16 * i][kk << 1]);
#pragma unroll
            for (int j = 0; j < 2; j++)
                w2[j] = *reinterpret_cast<const u64*>(&Ws[tn + 16 * j][kk << 1]);
#pragma unroll
            for (int i = 0; i < 4; i++)
#pragma unroll
                for (int j = 0; j < 2; j++) fma2(acc[i][j], a2[i], w2[j]);
        }
        __syncthreads();
    }
    float* out = P + (long)blockIdx.y * 64 * N;
#pragma unroll
    for (int i = 0; i < 4; i++)
#pragma unroll
        for (int j = 0; j < 2; j++)
            out[(tm + 16 * i) * (long)N + n0 + tn + 16 * j] = pairsum(acc[i][j]);
}

// ---------------- persistent LSTM machinery ----------------
__device__ __forceinline__ void step_gemm(const float* __restrict__ A, int lda,
                                          const float* __restrict__ W,
                                          float* __restrict__ part, int bx)
{
    __shared__ float As[64][34];
    __shared__ float Ws[32][34];
    const int tid  = threadIdx.x;
    const int n0   = (bx & 63) * 32;
    const int kb   = (bx >> 6) * 256;
    const int tm   = tid >> 4;
    const int tn   = tid & 15;
    const int lrow = tid >> 3;
    const int lcol = (tid & 7) << 2;

    u64 acc[4][2];
#pragma unroll
    for (int i = 0; i < 4; i++) { acc[i][0] = 0ull; acc[i][1] = 0ull; }

    float4 pa0, pa1, pw;
    {
        int k = kb + lcol;
        pa0 = *reinterpret_cast<const float4*>(A + (long)lrow * lda + k);
        pa1 = *reinterpret_cast<const float4*>(A + (long)(lrow + 32) * lda + k);
        pw  = *reinterpret_cast<const float4*>(W + (long)(n0 + lrow) * CH + k);
    }
    for (int c = 0; c < 8; c++) {
        sts4(&As[lrow][lcol],      pa0);
        sts4(&As[lrow + 32][lcol], pa1);
        sts4(&Ws[lrow][lcol],      pw);
        __syncthreads();
        if (c < 7) {
            int k = kb + ((c + 1) << 5) + lcol;
            pa0 = *reinterpret_cast<const float4*>(A + (long)lrow * lda + k);
            pa1 = *reinterpret_cast<const float4*>(A + (long)(lrow + 32) * lda + k);
            pw  = *reinterpret_cast<const float4*>(W + (long)(n0 + lrow) * CH + k);
        }
#pragma unroll
        for (int kk = 0; kk < 16; kk++) {
            u64 a2[4], w2[2];
#pragma unroll
            for (int i = 0; i < 4; i++)
                a2[i] = *reinterpret_cast<const u64*>(&As[tm + 16 * i][kk << 1]);
#pragma unroll
            for (int j = 0; j < 2; j++)
                w2[j] = *reinterpret_cast<const u64*>(&Ws[tn + 16 * j][kk << 1]);
#pragma unroll
            for (int i = 0; i < 4; i++)
#pragma unroll
                for (int j = 0; j < 2; j++) fma2(acc[i][j], a2[i], w2[j]);
        }
        __syncthreads();
    }
    float* out = part + (long)(bx >> 6) * 64 * G4;
#pragma unroll
    for (int i = 0; i < 4; i++)
#pragma unroll
        for (int j = 0; j < 2; j++)
            out[(tm + 16 * i) * G4 + n0 + tn + 16 * j] = pairsum(acc[i][j]);
}

__device__ __forceinline__ void gates_fn(const float* P, const float* D1, int ldd1,
                                         const float* D2, float* c,
                                         float* h_out, int h_ld, int idx,
                                         __nv_bfloat16* hs, long hs_losz)
{
    int b = idx >> 9, u = idx & 511;
    const float* g0 = P + (long)b * G4;
    const float* g1 = P + (long)CB * G4 + (long)b * G4;
    const float* d1 = D1 + (long)b * ldd1;
    float gi = g0[u]        + g1[u]        + d1[u];
    float gf = g0[512 + u]  + g1[512 + u]  + d1[512 + u];
    float gg = g0[1024 + u] + g1[1024 + u] + d1[1024 + u];
    float go = g0[1536 + u] + g1[1536 + u] + d1[1536 + u];
    if (D2) {
        const float* d2 = D2 + (long)b * G4;
        gi += d2[u]; gf += d2[512 + u]; gg += d2[1024 + u]; go += d2[1536 + u];
    }
    float i_ = 1.f / (1.f + expf(-gi));
    float f_ = 1.f / (1.f + expf(-gf));
    float g_ = tanhf(gg);
    float o_ = 1.f / (1.f + expf(-go));
    float cn = f_ * c[idx] + i_ * g_;
    c[idx] = cn;
    float hv = o_ * tanhf(cn);
    long lin = (long)b * h_ld + u;
    h_out[lin] = hv;
    if (hs) {
        __nv_bfloat16 hh, hl; split1(hv, hh, hl);
        hs[lin] = hh;
        hs[lin + hs_losz] = hl;
    }
}

// ---- fused fwd+bwd encoder LSTMs: interleaved phases, ONE barrier per phase ----
__global__ __launch_bounds__(256) void enc_lstm2(
    const float* __restrict__ Whh_f, const float* __restrict__ Whh_b,
    const float* __restrict__ ginF,  const float* __restrict__ ginB,
    float* __restrict__ hF, float* __restrict__ hB,
    float* __restrict__ cF, float* __restrict__ cB2,
    const float* __restrict__ hz,
    float* __restrict__ partF, float* __restrict__ partB)
{
    unsigned target = 0;
    const int bx  = blockIdx.x;
    const int idx = bx * 256 + threadIdx.x;
    for (int p = 0; p < 2 * CL; p++) {
        const int li = p & 1;            // 0 = fwd, 1 = bwd
        const int s  = p >> 1;
        const float* Whh  = li ? Whh_b : Whh_f;
        const float* gin  = li ? ginB  : ginF;
        float* hbase = li ? hB : hF;
        float* cc    = li ? cB2 : cF;
        float* part  = li ? partB : partF;
        const int l = li ? (CL - 1 - s) : s;
        const float* hin;
        if (s == 0) hin = hz;
        else {
            int lp = li ? (l + 1) : (l - 1);
            hin = hbase + (long)lp * CB * CH;
        }
        step_gemm(hin, CH, Whh, part, bx);
        grid_bar(target);                 // part(li,s) complete across all blocks
        gates_fn(part, gin + (long)l * G4, CL * G4, nullptr, cc,
                 hbase + (long)l * CB * CH, CH, idx, nullptr, 0);
        // h(li,s) consumed by gemm(li,s+1) two phases later -> guarded by next grid_bar
    }
    grid_bar_final(target);               // reset counter for next persistent launch
}

// ---- decoder persistent LSTM (2 barriers per step; writes bf16 split of h) ----
__global__ __launch_bounds__(256) void lstm_persist(
    const float* __restrict__ Whh,
    const float* __restrict__ gin, long gin_step, int gin_ld,
    const float* __restrict__ D2,
    const float* __restrict__ hz,
    float* __restrict__ hbase, long h_step, int h_ld,
    float* __restrict__ c, float* __restrict__ part,
    int nsteps,
    __nv_bfloat16* __restrict__ hs, long hs_losz)
{
    unsigned target = 0;
    const int bx  = blockIdx.x;
    const int idx = bx * 256 + threadIdx.x;
    for (int s = 0; s < nsteps; s++) {
        const float* hin = (s == 0) ? hz : hbase + (long)(s - 1) * h_step;
        int hlda = (s == 0) ? CH : h_ld;
        step_gemm(hin, hlda, Whh, part, bx);
        grid_bar(target);
        gates_fn(part, gin + (long)s * gin_step, gin_ld, D2, c,
                 hbase + (long)s * h_step, h_ld, idx,
                 hs ? hs + (long)s * h_step : nullptr, hs_losz);
        if (s + 1 < nsteps) grid_bar(target);  // h(s) visible before gemm(s+1)
        else                grid_bar_final(target);
    }
}

// ---------------- small elementwise kernels ----------------
__global__ void zero_state(float* cF, float* cB, float* cD, float* hz)
{
    int idx = blockIdx.x * blockDim.x + threadIdx.x;
    cF[idx] = 0.f; cB[idx] = 0.f; cD[idx] = 0.f; hz[idx] = 0.f;
}

// zero pad rows (2496..2559) of DEMB and HD splits (hi and lo)
__global__ void zero_bf_pads(__nv_bfloat16* base)
{
    int i = blockIdx.x * 256 + threadIdx.x;   // 0..32767 = 64*512
    long r = 2496L * 512 + i;
    base[BO_DEMB + r] = __float2bfloat16(0.f);
    base[BO_DEMB + 2560L * 512 + r] = __float2bfloat16(0.f);
    base[BO_HD + r] = __float2bfloat16(0.f);
    base[BO_HD + 2560L * 512 + r] = __float2bfloat16(0.f);
}

__global__ void ctx_sum(const float* __restrict__ hF, const float* __restrict__ hB,
                        float* __restrict__ ctx)
{
    int idx = blockIdx.x * blockDim.x + threadIdx.x;  // 64*1024
    int b = idx >> 10, j = idx & 1023;
    float s = 0.f;
    if (j < 512) {
        for (int l = 0; l < CL; l++) s += hF[((long)l * CB + b) * CH + j];
    } else {
        int j2 = j - 512;
        for (int l = 0; l < CL; l++) s += hB[((long)l * CB + b) * CH + j2];
    }
    ctx[idx] = s;
}

__global__ void ctx_combine(const float* __restrict__ P,
                            const float* __restrict__ b0,
                            const float* __restrict__ b1,
                            float* __restrict__ ctxW)
{
    int idx = blockIdx.x * blockDim.x + threadIdx.x;  // 64*2048
    int b = idx >> 11, n = idx & 2047;
    float s = b0[n] + b1[n];
#pragma unroll
    for (int z = 0; z < 4; z++) s += P[((long)z * CB + b) * G4 + n];
    ctxW[idx] = s;
}

// embedding gather writing bf16 hi/lo split directly
__global__ void gather_emb_split(const float* __restrict__ emb, const int* __restrict__ targets,
                                 __nv_bfloat16* __restrict__ dst, long losz)
{
    int idx = blockIdx.x * blockDim.x + threadIdx.x;  // 39*64*512
    int e = idx & 511;
    int r = idx >> 9;
    int t = r / CB, b = r - t * CB;
    int tgt = targets[b * CL + t];
    float v = emb[(long)tgt * CE + e];
    __nv_bfloat16 h, l; split1(v, h, l);
    dst[idx] = h;
    dst[idx + losz] = l;
}

// ---------------- launch ----------------
static inline int sgrid(long n) { return (int)((n + 255) / 256); }

extern "C" void kernel_launch(void* const* d_in, const int* in_sizes, int n_in,
                              void* d_out, int out_size)
{
    (void)in_sizes; (void)n_in; (void)out_size;
    const float* feats  = (const float*)d_in[0];
    const float* feat_W = (const float*)d_in[1];
    const float* feat_b = (const float*)d_in[2];
    const float* Wih_f  = (const float*)d_in[3];
    const float* Whh_f  = (const float*)d_in[4];
    const float* bih_f  = (const float*)d_in[5];
    const float* bhh_f  = (const float*)d_in[6];
    const float* Wih_b  = (const float*)d_in[7];
    const float* Whh_b  = (const float*)d_in[8];
    const float* bih_b  = (const float*)d_in[9];
    const float* bhh_b  = (const float*)d_in[10];
    const float* emb    = (const float*)d_in[11];
    const float* Wih_d  = (const float*)d_in[12];
    const float* Whh_d  = (const float*)d_in[13];
    const float* bih_d  = (const float*)d_in[14];
    const float* bhh_d  = (const float*)d_in[15];
    // d_in[16..20]: attention params — provably unused (softmax over singleton axis -> ones)
    const float* out_W  = (const float*)d_in[21];
    const float* out_b  = (const float*)d_in[22];
    const int*   targets = (const int*)d_in[23];
    float* out = (float*)d_out;

    float* S = nullptr;
    cudaGetSymbolAddress((void**)&S, g_scratch);
    __nv_bfloat16* BF = nullptr;
    cudaGetSymbolAddress((void**)&BF, g_bf);

    float* ginF  = S + OFF_GINF;
    float* ginB  = S + OFF_GINB;
    float* hF    = S + OFF_HF;
    float* hB    = S + OFF_HB;
    float* hD    = S + OFF_HD;
    float* cF    = S + OFF_CF;
    float* cBb   = S + OFF_CB2;
    float* cD    = S + OFF_CD;
    float* hz    = S + OFF_HZ;
    float* ctx   = S + OFF_CTX;
    float* embW  = S + OFF_EMBW;
    float* ctxW  = S + OFF_CTXW;
    float* part  = S + OFF_PART;                    // partF = part, partB = part + 2*CB*G4
    float* partB = part + 2L * CB * G4;

    cudaFuncSetAttribute(gemm_mma, cudaFuncAttributeMaxDynamicSharedMemorySize, MMA_SMEM);

    zero_state<<<128, 256>>>(cF, cBb, cD, hz);
    zero_bf_pads<<<128, 256>>>(BF);

    // ---- weight/input splits to bf16 hi/lo ----
    split_bf16<<<sgrid(20096L*512), 256>>>(out_W, 512, 20000, 512,
                                           BF + BO_WOUT, 20096L*512, 20096L*512);
    split_bf16<<<sgrid(512L*2048), 256>>>(feat_W, 2048, 512, 2048,
                                          BF + BO_FW, 512L*2048, 512L*2048);
    split_bf16<<<sgrid(2048L*512), 256>>>(Wih_f, 512, 2048, 512,
                                          BF + BO_WIF, 2048L*512, 2048L*512);
    split_bf16<<<sgrid(2048L*512), 256>>>(Wih_b, 512, 2048, 512,
                                          BF + BO_WIB, 2048L*512, 2048L*512);
    split_bf16<<<sgrid(2048L*512), 256>>>(Wih_d, 2*CH + CE, 2048, 512,
                                          BF + BO_WID, 2048L*512, 2048L*512);
    split_bf16<<<sgrid(2560L*2048), 256>>>(feats, 2048, 2560, 2048,
                                           BF + BO_FEATS, 2560L*2048, 2560L*2048);

    // x = feats @ feat_W^T + feat_b  -> written DIRECTLY as bf16 hi/lo split
    gemm_mma<<<dim3(20, 4), 256, MMA_SMEM>>>(BF + BO_FEATS, 2560L*2048, BF + BO_FW, 512L*2048,
                                             nullptr, CH, 2560, CH, CDF, feat_b, nullptr,
                                             BF + BO_X, 2560L*512);

    // encoder input-gate precompute
    gemm_mma<<<dim3(20, 16), 256, MMA_SMEM>>>(BF + BO_X, 2560L*512, BF + BO_WIF, 2048L*512,
                                              ginF, G4, 2560, G4, CH, bih_f, bhh_f, nullptr, 0);
    gemm_mma<<<dim3(20, 16), 256, MMA_SMEM>>>(BF + BO_X, 2560L*512, BF + BO_WIB, 2048L*512,
                                              ginB, G4, 2560, G4, CH, bih_b, bhh_b, nullptr, 0);

    // fused fwd+bwd encoder LSTMs (interleaved phases, atomic grid barrier)
    enc_lstm2<<<128, 256>>>(Whh_f, Whh_b, ginF, ginB, hF, hB, cF, cBb, hz, part, partB);

    // ctx[b] = sum_l enc[b,l,:]  (attention collapses: softmax over singleton axis)
    ctx_sum<<<256, 256>>>(hF, hB, ctx);

    // decoder input-gate precompute (gather writes bf16 split directly)
    gather_emb_split<<<(CT * CB * CE) / 256, 256>>>(emb, targets, BF + BO_DEMB, 2560L*512);
    gemm_mma<<<dim3(20, 16), 256, MMA_SMEM>>>(BF + BO_DEMB, 2560L*512, BF + BO_WID, 2048L*512,
                                              embW, G4, 2496, G4, CE, nullptr, nullptr,
                                              nullptr, 0);
    gemm_small64<<<dim3(64, 4), 256>>>(ctx, 2 * CH, Wih_d + CE, 2 * CH + CE, part, G4, 256);
    ctx_combine<<<512, 256>>>(part, bih_d, bhh_d, ctxW);

    // decoder LSTM persistent (hD layout [B][T][H]; gates also write bf16 split of hD)
    lstm_persist<<<128, 256>>>(Whh_d, embW, (long)CB * G4, G4, ctxW, hz,
                               hD, (long)CH, CT * CH, cD, part, CT,
                               BF + BO_HD, 2560L*512);

    // output projection: out[b,t,:] = hD[b,t,:] @ out_W^T + out_b  (HMMA)
    gemm_mma<<<dim3(20, 157), 256, MMA_SMEM>>>(BF + BO_HD, 2560L*512, BF + BO_WOUT, 20096L*512,
                                               out, CV, 2496, CV, CH, out_b, nullptr,
                                               nullptr, 0);
}

// round 16
// speedup vs baseline: 1.9586x; 1.3838x over previous
#include <cuda_runtime.h>
#include <cuda_bf16.h>
#include <math.h>
#include <stdint.h>

// Problem dims
#define CB   64      // batch
#define CL   40      // seq len
#define CT   39      // decoder steps (L-1)
#define CH   512     // hidden
#define CDF  2048    // feature dim
#define CE   512     // embedding dim
#define CV   20000   // vocab
#define G4   2048    // 4*H

typedef unsigned long long u64;

// ---------------- fp32 scratch ----------------
constexpr int OFF_X    = 0;
constexpr int OFF_GINF = OFF_X    + CB*CL*CH;
constexpr int OFF_GINB = OFF_GINF + CB*CL*G4;
constexpr int OFF_HF   = OFF_GINB + CB*CL*G4;
constexpr int OFF_HB   = OFF_HF   + CL*CB*CH;
constexpr int OFF_HD   = OFF_HB   + CL*CB*CH;     // (fp32 hD retained but unused)
constexpr int OFF_CF   = OFF_HD   + CB*CT*CH;
constexpr int OFF_CB2  = OFF_CF   + CB*CH;
constexpr int OFF_CD   = OFF_CB2  + CB*CH;
constexpr int OFF_HZ   = OFF_CD   + CB*CH;
constexpr int OFF_CTX  = OFF_HZ   + CB*CH;
constexpr int OFF_DEMB = OFF_CTX  + CB*2*CH;
constexpr int OFF_EMBW = OFF_DEMB + CT*CB*CE;
constexpr int OFF_CTXW = OFF_EMBW + CT*CB*G4;
constexpr int OFF_PART = OFF_CTXW + CB*G4;
constexpr int SCRATCH_TOTAL = OFF_PART + 16*CB*G4;   // part: 8 slices x2 directions
__device__ __align__(256) float g_scratch[SCRATCH_TOTAL];
__device__ unsigned g_bar = 0;   // atomic barrier counter (always 0 between launches)

// ---------------- bf16 hi/lo scratch (hi at off, lo at off + PLANE size) ----------
constexpr long BO_WOUT  = 0;                               // 20096 x 512 (pad of 20000)
constexpr long BO_FW    = BO_WOUT  + 2L*20096*512;         // 512 x 2048
constexpr long BO_WIF   = BO_FW    + 2L*512*2048;          // 2048 x 512
constexpr long BO_WIB   = BO_WIF   + 2L*2048*512;
constexpr long BO_WID   = BO_WIB   + 2L*2048*512;          // 2048 x 512 (first E cols)
constexpr long BO_FEATS = BO_WID   + 2L*2048*512;          // 2560 x 2048
constexpr long BO_X     = BO_FEATS + 2L*2560*2048;         // 2560 x 512
constexpr long BO_DEMB  = BO_X     + 2L*2560*512;          // 2560 x 512 (pad of 2496)
constexpr long BO_HD    = BO_DEMB  + 2L*2560*512;          // 2560 x 512 (pad of 2496)
constexpr long BO_WHF   = BO_HD    + 2L*2560*512;          // 2048 x 512 (Whh_f split)
constexpr long BO_WHB   = BO_WHF   + 2L*2048*512;
constexpr long BO_WHD   = BO_WHB   + 2L*2048*512;
constexpr long BO_HFS   = BO_WHD   + 2L*2048*512;          // [CL][CB][CH] h split fwd
constexpr long BO_HBS   = BO_HFS   + 2L*CL*CB*CH;
constexpr long BO_HZS   = BO_HBS   + 2L*CL*CB*CH;          // zero h split (64x512)
constexpr long BF_TOTAL = BO_HZS   + 2L*CB*CH;
__device__ __align__(256) __nv_bfloat16 g_bf[BF_TOTAL];

// lo-plane offset (ELEMENT count of ONE plane) for the Whh splits — R14's bug was
// passing the 2-plane total (2L*2048*512) here.
constexpr long WH_LOSZ = 2048L * 512;

// ---------------- helpers ----------------
__device__ __forceinline__ void fma2(u64 &d, u64 a, u64 b) {
    asm("fma.rn.f32x2 %0, %1, %2, %0;" : "+l"(d) : "l"(a), "l"(b));
}
__device__ __forceinline__ float pairsum(u64 v) {
    float lo = __uint_as_float((unsigned)(v & 0xffffffffull));
    float hi = __uint_as_float((unsigned)(v >> 32));
    return lo + hi;
}
__device__ __forceinline__ void sts4(float* dst, float4 v) {
    *reinterpret_cast<float2*>(dst)     = make_float2(v.x, v.y);
    *reinterpret_cast<float2*>(dst + 2) = make_float2(v.z, v.w);
}
__device__ __forceinline__ uint32_t smem_u32(const void* p) {
    uint32_t a;
    asm("{ .reg .u64 t; cvta.to.shared.u64 t, %1; cvt.u32.u64 %0, t; }" : "=r"(a) : "l"(p));
    return a;
}
__device__ __forceinline__ void cp16(uint32_t dst, const void* src) {
    asm volatile("cp.async.cg.shared.global [%0], [%1], 16;" :: "r"(dst), "l"(src) : "memory");
}
__device__ __forceinline__ void cp_commit() {
    asm volatile("cp.async.commit_group;" ::: "memory");
}
__device__ __forceinline__ void cp_wait0() {
    asm volatile("cp.async.wait_group 0;" ::: "memory");
}
__device__ __forceinline__ void cp_wait1() {
    asm volatile("cp.async.wait_group 1;" ::: "memory");
}
__device__ __forceinline__ void ldsm4(uint32_t* r, uint32_t addr) {
    asm volatile("ldmatrix.sync.aligned.m8n8.x4.shared.b16 {%0,%1,%2,%3}, [%4];"
                 : "=r"(r[0]), "=r"(r[1]), "=r"(r[2]), "=r"(r[3]) : "r"(addr));
}
__device__ __forceinline__ void mma16816(float* d, const uint32_t* a, const uint32_t* b) {
    asm volatile("mma.sync.aligned.m16n8k16.row.col.f32.bf16.bf16.f32 "
                 "{%0,%1,%2,%3}, {%4,%5,%6,%7}, {%8,%9}, {%0,%1,%2,%3};"
                 : "+f"(d[0]), "+f"(d[1]), "+f"(d[2]), "+f"(d[3])
                 : "r"(a[0]), "r"(a[1]), "r"(a[2]), "r"(a[3]), "r"(b[0]), "r"(b[1]));
}
// swizzled element index for (row r, k-chunk c) in a [128][32] bf16 tile; 8 elems/chunk.
__device__ __forceinline__ int swzi(int r, int c) {
    int cc = (c + r + (r >> 2)) & 3;
    return r * 32 + cc * 8;
}
// BYTE offset for (row r, 16B-chunk c8) in a [rows][64] bf16 tile (128B rows, XOR swizzle)
__device__ __forceinline__ uint32_t sw64(int r, int c8) {
    return (uint32_t)((r << 7) + (((c8 ^ (r & 7)) & 7) << 4));
}
__device__ __forceinline__ void split1(float v, __nv_bfloat16& h, __nv_bfloat16& l) {
    h = __float2bfloat16(v);
    l = __float2bfloat16(v - __bfloat162float(h));
}

// ---------------- atomic-counter grid barrier (128 resident blocks) ----------------
__device__ __forceinline__ void grid_bar(unsigned &target) {
    __syncthreads();
    target += 128u;
    if (threadIdx.x == 0) {
        __threadfence();                       // release
        atomicAdd(&g_bar, 1u);
        unsigned v;
        do {
            asm volatile("ld.volatile.global.u32 %0, [%1];" : "=r"(v) : "l"(&g_bar));
        } while (v < target);
        __threadfence();                       // acquire
    }
    __syncthreads();
}
__device__ __forceinline__ void grid_bar_final(unsigned target) {
    __syncthreads();
    if (threadIdx.x == 0) {
        __threadfence();
        unsigned old = atomicAdd(&g_bar, 1u);
        if (old == target + 127u) {            // last arriver resets for next launch
            __threadfence();
            asm volatile("st.volatile.global.u32 [%0], %1;" :: "l"(&g_bar), "r"(0u));
        }
    }
}

// ================= split fp32 -> bf16 hi/lo (with row padding to zeros) ============
__global__ void split_bf16(const float* __restrict__ src, int ld, int rows_valid, int cols,
                           __nv_bfloat16* __restrict__ hi, long losz, long total)
{
    long idx = (long)blockIdx.x * 256 + threadIdx.x;
    if (idx >= total) return;
    long r = idx / cols;
    int  c = (int)(idx - r * cols);
    float v = (r < rows_valid) ? src[r * (long)ld + c] : 0.f;
    __nv_bfloat16 h, l; split1(v, h, l);
    hi[idx]        = h;
    hi[idx + losz] = l;
}

// ================= HMMA GEMM (double-buffered): C = A * W^T (+b0+b1) ==============
constexpr int MMA_STAGE_B = 32768;
constexpr int MMA_SMEM    = 2 * MMA_STAGE_B;

__global__ __launch_bounds__(256) void gemm_mma(
    const __nv_bfloat16* __restrict__ Ah, long Asz,
    const __nv_bfloat16* __restrict__ Wh, long Wsz,
    float* __restrict__ C, int ldc, int Mvalid, int N, int K,
    const float* __restrict__ bias0, const float* __restrict__ bias1,
    __nv_bfloat16* __restrict__ Csp, long Csp_losz)
{
    extern __shared__ __align__(128) __nv_bfloat16 dynsmem[];
    const uint32_t base = smem_u32(dynsmem);

    const int tid  = threadIdx.x;
    const int wid  = tid >> 5, lane = tid & 31;
    const int wm   = wid >> 2;
    const int wn   = wid & 3;
    const int m0   = blockIdx.x * 128, n0 = blockIdx.y * 128;

    const __nv_bfloat16* Al = Ah + Asz;
    const __nv_bfloat16* Wl = Wh + Wsz;

    float acc[4][4][4];
#pragma unroll
    for (int i = 0; i < 4; i++)
#pragma unroll
        for (int j = 0; j < 4; j++)
#pragma unroll
            for (int q = 0; q < 4; q++) acc[i][j][q] = 0.f;

    const int s_r0 = tid >> 2, s_c0 = tid & 3;
    const int s_r1 = (tid + 256) >> 2, s_c1 = tid & 3;
    const uint32_t so0 = (uint32_t)swzi(s_r0, s_c0) * 2;
    const uint32_t so1 = (uint32_t)swzi(s_r1, s_c1) * 2;

    const int a_r  = lane & 15;
    const int a_cg = lane >> 4;
    const int b_r  = (lane & 7) + ((lane >> 4) << 3);
    const int b_cg = (lane >> 3) & 1;

    const int nch = K >> 5;

    auto load_stage = [&](int c, uint32_t sb) {
        const int k0 = c << 5;
        long ga0 = (long)(m0 + s_r0) * K + k0 + s_c0 * 8;
        long gb0 = (long)(n0 + s_r0) * K + k0 + s_c0 * 8;
        cp16(sb +         so0, Ah + ga0);
        cp16(sb +  8192 + so0, Al + ga0);
        cp16(sb + 16384 + so0, Wh + gb0);
        cp16(sb + 24576 + so0, Wl + gb0);
        long ga1 = (long)(m0 + s_r1) * K + k0 + s_c1 * 8;
        long gb1 = (long)(n0 + s_r1) * K + k0 + s_c1 * 8;
        cp16(sb +         so1, Ah + ga1);
        cp16(sb +  8192 + so1, Al + ga1);
        cp16(sb + 16384 + so1, Wh + gb1);
        cp16(sb + 24576 + so1, Wl + gb1);
        cp_commit();
    };

    load_stage(0, base);

    for (int c = 0; c < nch; c++) {
        const uint32_t cb = base + (uint32_t)(c & 1) * MMA_STAGE_B;
        if (c + 1 < nch) {
            load_stage(c + 1, base + (uint32_t)((c + 1) & 1) * MMA_STAGE_B);
            cp_wait1();
        } else {
            cp_wait0();
        }
        __syncthreads();

        const uint32_t bAh = cb, bAl = cb + 8192, bWh = cb + 16384, bWl = cb + 24576;
#pragma unroll
        for (int h = 0; h < 2; h++) {
            uint32_t ah[4][4], al[4][4];
#pragma unroll
            for (int t = 0; t < 4; t++) {
                int r  = wm * 64 + t * 16 + a_r;
                int ch = 2 * h + a_cg;
                uint32_t off = (uint32_t)swzi(r, ch) * 2;
                ldsm4(ah[t], bAh + off);
                ldsm4(al[t], bAl + off);
            }
            uint32_t bh[4][2], bl[4][2];
#pragma unroll
            for (int p = 0; p < 2; p++) {
                int r  = wn * 32 + p * 16 + b_r;
                int ch = 2 * h + b_cg;
                uint32_t off = (uint32_t)swzi(r, ch) * 2;
                uint32_t tmp[4];
                ldsm4(tmp, bWh + off);
                bh[2*p][0] = tmp[0]; bh[2*p][1] = tmp[1];
                bh[2*p+1][0] = tmp[2]; bh[2*p+1][1] = tmp[3];
                ldsm4(tmp, bWl + off);
                bl[2*p][0] = tmp[0]; bl[2*p][1] = tmp[1];
                bl[2*p+1][0] = tmp[2]; bl[2*p+1][1] = tmp[3];
            }
#pragma unroll
            for (int t = 0; t < 4; t++)
#pragma unroll
                for (int n = 0; n < 4; n++) {
                    mma16816(acc[t][n], ah[t], bh[n]);
                    mma16816(acc[t][n], ah[t], bl[n]);
                    mma16816(acc[t][n], al[t], bh[n]);
                }
        }
        __syncthreads();
    }

#pragma unroll
    for (int t = 0; t < 4; t++) {
#pragma unroll
        for (int n = 0; n < 4; n++) {
            int row = m0 + wm * 64 + t * 16 + (lane >> 2);
            int col = n0 + wn * 32 + n * 8 + 2 * (lane & 3);
            if (col < N) {
                float bx = 0.f, by = 0.f;
                if (bias0) { bx += bias0[col]; by += bias0[col + 1]; }
                if (bias1) { bx += bias1[col]; by += bias1[col + 1]; }
#pragma unroll
                for (int half = 0; half < 2; half++) {
                    int r = row + 8 * half;
                    if (r < Mvalid) {
                        float vx = acc[t][n][2*half]     + bx;
                        float vy = acc[t][n][2*half + 1] + by;
                        if (C)
                            *reinterpret_cast<float2*>(C + (long)r * ldc + col) =
                                make_float2(vx, vy);
                        if (Csp) {
                            __nv_bfloat16 hx, lx, hy, ly;
                            split1(vx, hx, lx); split1(vy, hy, ly);
                            long o = (long)r * ldc + col;
                            Csp[o] = hx; Csp[o + 1] = hy;
                            Csp[o + Csp_losz] = lx; Csp[o + Csp_losz + 1] = ly;
                        }
                    }
                }
            }
        }
    }
}

// ---------------- small-M GEMM (used once for ctx @ Wih_d[:,E:]) ----------------
__global__ __launch_bounds__(256) void gemm_small64(
    const float* __restrict__ A, int lda,
    const float* __restrict__ W, int ldw,
    float* __restrict__ P, int N, int Kps)
{
    __shared__ float As[64][34];
    __shared__ float Ws[32][34];
    const int tid  = threadIdx.x;
    const int n0   = blockIdx.x * 32;
    const int kb   = blockIdx.y * Kps;
    const int tm   = tid >> 4;
    const int tn   = tid & 15;
    const int lrow = tid >> 3;
    const int lcol = (tid & 7) << 2;

    u64 acc[4][2];
#pragma unroll
    for (int i = 0; i < 4; i++) { acc[i][0] = 0ull; acc[i][1] = 0ull; }

    const int nk = Kps >> 5;
    float4 pa0, pa1, pw;
    {
        int k = kb + lcol;
        pa0 = *reinterpret_cast<const float4*>(A + (long)lrow * lda + k);
        pa1 = *reinterpret_cast<const float4*>(A + (long)(lrow + 32) * lda + k);
        pw  = *reinterpret_cast<const float4*>(W + (long)(n0 + lrow) * ldw + k);
    }
    for (int c = 0; c < nk; c++) {
        sts4(&As[lrow][lcol],      pa0);
        sts4(&As[lrow + 32][lcol], pa1);
        sts4(&Ws[lrow][lcol],      pw);
        __syncthreads();
        if (c + 1 < nk) {
            int k = kb + ((c + 1) << 5) + lcol;
            pa0 = *reinterpret_cast<const float4*>(A + (long)lrow * lda + k);
            pa1 = *reinterpret_cast<const float4*>(A + (long)(lrow + 32) * lda + k);
            pw  = *reinterpret_cast<const float4*>(W + (long)(n0 + lrow) * ldw + k);
        }
#pragma unroll
        for (int kk = 0; kk < 16; kk++) {
            u64 a2[4], w2[2];
#pragma unroll
            for (int i = 0; i < 4; i++)
                a2[i] = *reinterpret_cast<const u64*>(&As[tm + 16 * i][kk << 1]);
#pragma unroll
            for (int j = 0; j < 2; j++)
                w2[j] = *reinterpret_cast<const u64*>(&Ws[tn + 16 * j][kk << 1]);
#pragma unroll
            for (int i = 0; i < 4; i++)
#pragma unroll
                for (int j = 0; j < 2; j++) fma2(acc[i][j], a2[i], w2[j]);
        }
        __syncthreads();
    }
    float* out = P + (long)blockIdx.y * 64 * N;
#pragma unroll
    for (int i = 0; i < 4; i++)
#pragma unroll
        for (int j = 0; j < 2; j++)
            out[(tm + 16 * i) * (long)N + n0 + tn + 16 * j] = pairsum(acc[i][j]);
}

// ---------------- persistent LSTM machinery (HMMA step GEMM) ----------------
// Step GEMM via HMMA bf16x3: part[kz][64][2048] = h[64,512] x Whh[2048,512]^T slice.
// 128 blocks = 16 n-tiles(128 cols) x 8 k-slices(64). Block tile M=64,N=128,K=64.
__device__ __forceinline__ void step_gemm_mma(
    const __nv_bfloat16* __restrict__ Ah, long Alosz, int lda,
    const __nv_bfloat16* __restrict__ Wh, long Wlosz,
    float* __restrict__ part, int bx,
    uint32_t bAh, uint32_t bAl, uint32_t bBh, uint32_t bBl)
{
    const int tid  = threadIdx.x;
    const int wid  = tid >> 5, lane = tid & 31;
    const int wm   = wid >> 2;        // 0..1 (32 rows each)
    const int wn   = wid & 3;         // 0..3 (32 cols each)
    const int kz   = bx >> 4;         // 0..7
    const int nb   = bx & 15;         // 0..15
    const int k0   = kz << 6;
    const int n0   = nb << 7;

    const __nv_bfloat16* Al_ = Ah + Alosz;
    const __nv_bfloat16* Wl_ = Wh + Wlosz;

    // ---- fill tiles (cp.async) ----
#pragma unroll
    for (int u = tid; u < 512; u += 256) {         // A: 64 rows x 8 chunks
        int r = u >> 3, c = u & 7;
        uint32_t so = sw64(r, c);
        long g = (long)r * lda + k0 + c * 8;
        cp16(bAh + so, Ah  + g);
        cp16(bAl + so, Al_ + g);
    }
#pragma unroll
    for (int u = tid; u < 1024; u += 256) {        // B: 128 rows x 8 chunks
        int r = u >> 3, c = u & 7;
        uint32_t so = sw64(r, c);
        long g = (long)(n0 + r) * CH + k0 + c * 8;
        cp16(bBh + so, Wh  + g);
        cp16(bBl + so, Wl_ + g);
    }
    cp_commit(); cp_wait0();
    __syncthreads();

    float acc[2][4][4];
#pragma unroll
    for (int i = 0; i < 2; i++)
#pragma unroll
        for (int j = 0; j < 4; j++)
#pragma unroll
            for (int q = 0; q < 4; q++) acc[i][j][q] = 0.f;

    const int a_r  = lane & 15;
    const int a_cg = lane >> 4;
    const int b_r  = (lane & 7) + ((lane >> 4) << 3);
    const int b_cg = (lane >> 3) & 1;

#pragma unroll
    for (int h = 0; h < 4; h++) {                  // 4 k16 steps (K=64)
        uint32_t ah[2][4], al[2][4];
#pragma unroll
        for (int t = 0; t < 2; t++) {
            int r  = wm * 32 + t * 16 + a_r;
            int ch = 2 * h + a_cg;
            ldsm4(ah[t], bAh + sw64(r, ch));
            ldsm4(al[t], bAl + sw64(r, ch));
        }
        uint32_t bh[4][2], bl[4][2];
#pragma unroll
        for (int p = 0; p < 2; p++) {
            int r  = wn * 32 + p * 16 + b_r;
            int ch = 2 * h + b_cg;
            uint32_t tmp[4];
            ldsm4(tmp, bBh + sw64(r, ch));
            bh[2*p][0] = tmp[0]; bh[2*p][1] = tmp[1];
            bh[2*p+1][0] = tmp[2]; bh[2*p+1][1] = tmp[3];
            ldsm4(tmp, bBl + sw64(r, ch));
            bl[2*p][0] = tmp[0]; bl[2*p][1] = tmp[1];
            bl[2*p+1][0] = tmp[2]; bl[2*p+1][1] = tmp[3];
        }
#pragma unroll
        for (int t = 0; t < 2; t++)
#pragma unroll
            for (int n = 0; n < 4; n++) {
                mma16816(acc[t][n], ah[t], bh[n]);
                mma16816(acc[t][n], ah[t], bl[n]);
                mma16816(acc[t][n], al[t], bh[n]);
            }
    }

    // ---- write partial slice ----
    float* outp = part + (long)kz * (CB * G4);
#pragma unroll
    for (int t = 0; t < 2; t++)
#pragma unroll
        for (int n = 0; n < 4; n++) {
            int row = wm * 32 + t * 16 + (lane >> 2);
            int col = n0 + wn * 32 + n * 8 + 2 * (lane & 3);
            *reinterpret_cast<float2*>(outp + (long)row * G4 + col) =
                make_float2(acc[t][n][0], acc[t][n][1]);
            *reinterpret_cast<float2*>(outp + (long)(row + 8) * G4 + col) =
                make_float2(acc[t][n][2], acc[t][n][3]);
        }
}

// gates: G = sum_z part[z] + D1 (+D2); update c; write h (fp32 optional) + bf16 split
__device__ __forceinline__ void gates_fn(const float* P, const float* D1, int ldd1,
                                         const float* D2, float* c,
                                         float* h_out, int h_ld, int idx,
                                         __nv_bfloat16* hs, long hs_losz)
{
    int b = idx >> 9, u = idx & 511;
    const float* d1 = D1 + (long)b * ldd1;
    float gi = d1[u], gf = d1[512 + u], gg = d1[1024 + u], go = d1[1536 + u];
#pragma unroll
    for (int z = 0; z < 8; z++) {
        const float* gz = P + (long)z * (CB * G4) + (long)b * G4;
        gi += gz[u]; gf += gz[512 + u]; gg += gz[1024 + u]; go += gz[1536 + u];
    }
    if (D2) {
        const float* d2 = D2 + (long)b * G4;
        gi += d2[u]; gf += d2[512 + u]; gg += d2[1024 + u]; go += d2[1536 + u];
    }
    float i_ = 1.f / (1.f + expf(-gi));
    float f_ = 1.f / (1.f + expf(-gf));
    float g_ = tanhf(gg);
    float o_ = 1.f / (1.f + expf(-go));
    float cn = f_ * c[idx] + i_ * g_;
    c[idx] = cn;
    float hv = o_ * tanhf(cn);
    long lin = (long)b * h_ld + u;
    if (h_out) h_out[lin] = hv;
    __nv_bfloat16 hh, hl; split1(hv, hh, hl);
    hs[lin] = hh;
    hs[lin + hs_losz] = hl;
}

// ---- fused fwd+bwd encoder LSTMs: interleaved phases, one barrier per phase ----
__global__ __launch_bounds__(256) void enc_lstm2(
    const __nv_bfloat16* __restrict__ whfS, const __nv_bfloat16* __restrict__ whbS,
    const float* __restrict__ ginF,  const float* __restrict__ ginB,
    float* __restrict__ hF, float* __restrict__ hB,
    __nv_bfloat16* __restrict__ hFs, __nv_bfloat16* __restrict__ hBs,
    const __nv_bfloat16* __restrict__ hzs,
    float* __restrict__ cF, float* __restrict__ cB2,
    float* __restrict__ partF, float* __restrict__ partB)
{
    __shared__ __align__(128) __nv_bfloat16 sA[2][64 * 64];
    __shared__ __align__(128) __nv_bfloat16 sB[2][128 * 64];
    const uint32_t bAh = smem_u32(sA[0]), bAl = smem_u32(sA[1]);
    const uint32_t bBh = smem_u32(sB[0]), bBl = smem_u32(sB[1]);
    constexpr long HS_LOSZ = (long)CL * CB * CH;
    constexpr long HZ_LOSZ = (long)CB * CH;

    unsigned target = 0;
    const int bx  = blockIdx.x;
    const int idx = bx * 256 + threadIdx.x;
    for (int p = 0; p < 2 * CL; p++) {
        const int li = p & 1;            // 0 = fwd, 1 = bwd
        const int s  = p >> 1;
        const __nv_bfloat16* whS = li ? whbS : whfS;
        const float* gin  = li ? ginB  : ginF;
        float* hbase = li ? hB : hF;
        __nv_bfloat16* hsb = li ? hBs : hFs;
        float* cc    = li ? cB2 : cF;
        float* part  = li ? partB : partF;
        const int l = li ? (CL - 1 - s) : s;
        const __nv_bfloat16* hin; long hlosz;
        if (s == 0) { hin = hzs; hlosz = HZ_LOSZ; }
        else {
            int lp = li ? (l + 1) : (l - 1);
            hin = hsb + (long)lp * CB * CH; hlosz = HS_LOSZ;
        }
        step_gemm_mma(hin, hlosz, CH, whS, WH_LOSZ, part, bx,
                      bAh, bAl, bBh, bBl);
        grid_bar(target);                 // part(li,s) complete across all blocks
        gates_fn(part, gin + (long)l * G4, CL * G4, nullptr, cc,
                 hbase + (long)l * CB * CH, CH, idx,
                 hsb + (long)l * CB * CH, HS_LOSZ);
        // h(li,s) consumed by gemm(li,s+1) two phases later -> guarded by next grid_bar
    }
    grid_bar_final(target);
}

// ---- decoder persistent LSTM (2 barriers per step; bf16-split h in/out) ----
__global__ __launch_bounds__(256) void lstm_persist(
    const __nv_bfloat16* __restrict__ whS,
    const float* __restrict__ gin, long gin_step, int gin_ld,
    const float* __restrict__ D2,
    const __nv_bfloat16* __restrict__ hzs,
    __nv_bfloat16* __restrict__ hs, long hs_losz, int h_ld,
    float* __restrict__ c, float* __restrict__ part, int nsteps)
{
    __shared__ __align__(128) __nv_bfloat16 sA[2][64 * 64];
    __shared__ __align__(128) __nv_bfloat16 sB[2][128 * 64];
    const uint32_t bAh = smem_u32(sA[0]), bAl = smem_u32(sA[1]);
    const uint32_t bBh = smem_u32(sB[0]), bBl = smem_u32(sB[1]);

    unsigned target = 0;
    const int bx  = blockIdx.x;
    const int idx = bx * 256 + threadIdx.x;
    for (int s = 0; s < nsteps; s++) {
        const __nv_bfloat16* hin;
        long hlosz; int hlda;
        if (s == 0) { hin = hzs; hlosz = (long)CB * CH; hlda = CH; }
        else        { hin = hs + (long)(s - 1) * CH; hlosz = hs_losz; hlda = h_ld; }
        step_gemm_mma(hin, hlosz, hlda, whS, WH_LOSZ, part, bx,
                      bAh, bAl, bBh, bBl);
        grid_bar(target);
        gates_fn(part, gin + (long)s * gin_step, gin_ld, D2, c,
                 nullptr, h_ld, idx, hs + (long)s * CH, hs_losz);
        if (s + 1 < nsteps) grid_bar(target);
        else                grid_bar_final(target);
    }
}

// ---------------- small elementwise kernels ----------------
__global__ void zero_state(float* cF, float* cB, float* cD, float* hz)
{
    int idx = blockIdx.x * blockDim.x + threadIdx.x;
    cF[idx] = 0.f; cB[idx] = 0.f; cD[idx] = 0.f; hz[idx] = 0.f;
}

// zero pad rows of DEMB/HD splits + the hz bf16 split
__global__ void zero_bf_pads(__nv_bfloat16* base)
{
    int i = blockIdx.x * 256 + threadIdx.x;   // 0..32767
    long r = 2496L * 512 + i;
    __nv_bfloat16 z = __float2bfloat16(0.f);
    base[BO_DEMB + r] = z;
    base[BO_DEMB + 2560L * 512 + r] = z;
    base[BO_HD + r] = z;
    base[BO_HD + 2560L * 512 + r] = z;
    base[BO_HZS + i] = z;
    base[BO_HZS + 32768 + i] = z;
}

__global__ void ctx_sum(const float* __restrict__ hF, const float* __restrict__ hB,
                        float* __restrict__ ctx)
{
    int idx = blockIdx.x * blockDim.x + threadIdx.x;  // 64*1024
    int b = idx >> 10, j = idx & 1023;
    float s = 0.f;
    if (j < 512) {
        for (int l = 0; l < CL; l++) s += hF[((long)l * CB + b) * CH + j];
    } else {
        int j2 = j - 512;
        for (int l = 0; l < CL; l++) s += hB[((long)l * CB + b) * CH + j2];
    }
    ctx[idx] = s;
}

__global__ void ctx_combine(const float* __restrict__ P,
                            const float* __restrict__ b0,
                            const float* __restrict__ b1,
                            float* __restrict__ ctxW)
{
    int idx = blockIdx.x * blockDim.x + threadIdx.x;  // 64*2048
    int b = idx >> 11, n = idx & 2047;
    float s = b0[n] + b1[n];
#pragma unroll
    for (int z = 0; z < 4; z++) s += P[((long)z * CB + b) * G4 + n];
    ctxW[idx] = s;
}

__global__ void gather_emb_split(const float* __restrict__ emb, const int* __restrict__ targets,
                                 __nv_bfloat16* __restrict__ dst, long losz)
{
    int idx = blockIdx.x * blockDim.x + threadIdx.x;  // 39*64*512
    int e = idx & 511;
    int r = idx >> 9;
    int t = r / CB, b = r - t * CB;
    int tgt = targets[b * CL + t];
    float v = emb[(long)tgt * CE + e];
    __nv_bfloat16 h, l; split1(v, h, l);
    dst[idx] = h;
    dst[idx + losz] = l;
}

// ---------------- launch ----------------
static inline int sgrid(long n) { return (int)((n + 255) / 256); }

extern "C" void kernel_launch(void* const* d_in, const int* in_sizes, int n_in,
                              void* d_out, int out_size)
{
    (void)in_sizes; (void)n_in; (void)out_size;
    const float* feats  = (const float*)d_in[0];
    const float* feat_W = (const float*)d_in[1];
    const float* feat_b = (const float*)d_in[2];
    const float* Wih_f  = (const float*)d_in[3];
    const float* Whh_f  = (const float*)d_in[4];
    const float* bih_f  = (const float*)d_in[5];
    const float* bhh_f  = (const float*)d_in[6];
    const float* Wih_b  = (const float*)d_in[7];
    const float* Whh_b  = (const float*)d_in[8];
    const float* bih_b  = (const float*)d_in[9];
    const float* bhh_b  = (const float*)d_in[10];
    const float* emb    = (const float*)d_in[11];
    const float* Wih_d  = (const float*)d_in[12];
    const float* Whh_d  = (const float*)d_in[13];
    const float* bih_d  = (const float*)d_in[14];
    const float* bhh_d  = (const float*)d_in[15];
    // d_in[16..20]: attention params — provably unused (softmax over singleton axis -> ones)
    const float* out_W  = (const float*)d_in[21];
    const float* out_b  = (const float*)d_in[22];
    const int*   targets = (const int*)d_in[23];
    float* out = (float*)d_out;

    float* S = nullptr;
    cudaGetSymbolAddress((void**)&S, g_scratch);
    __nv_bfloat16* BF = nullptr;
    cudaGetSymbolAddress((void**)&BF, g_bf);

    float* ginF  = S + OFF_GINF;
    float* ginB  = S + OFF_GINB;
    float* hF    = S + OFF_HF;
    float* hB    = S + OFF_HB;
    float* cF    = S + OFF_CF;
    float* cBb   = S + OFF_CB2;
    float* cD    = S + OFF_CD;
    float* hz    = S + OFF_HZ;
    float* ctx   = S + OFF_CTX;
    float* embW  = S + OFF_EMBW;
    float* ctxW  = S + OFF_CTXW;
    float* part  = S + OFF_PART;                 // partF = part, partB = part + 8*CB*G4
    float* partB = part + 8L * CB * G4;

    cudaFuncSetAttribute(gemm_mma, cudaFuncAttributeMaxDynamicSharedMemorySize, MMA_SMEM);

    zero_state<<<128, 256>>>(cF, cBb, cD, hz);
    zero_bf_pads<<<128, 256>>>(BF);

    // ---- weight/input splits to bf16 hi/lo ----
    split_bf16<<<sgrid(20096L*512), 256>>>(out_W, 512, 20000, 512,
                                           BF + BO_WOUT, 20096L*512, 20096L*512);
    split_bf16<<<sgrid(512L*2048), 256>>>(feat_W, 2048, 512, 2048,
                                          BF + BO_FW, 512L*2048, 512L*2048);
    split_bf16<<<sgrid(2048L*512), 256>>>(Wih_f, 512, 2048, 512,
                                          BF + BO_WIF, 2048L*512, 2048L*512);
    split_bf16<<<sgrid(2048L*512), 256>>>(Wih_b, 512, 2048, 512,
                                          BF + BO_WIB, 2048L*512, 2048L*512);
    split_bf16<<<sgrid(2048L*512), 256>>>(Wih_d, 2*CH + CE, 2048, 512,
                                          BF + BO_WID, 2048L*512, 2048L*512);
    split_bf16<<<sgrid(2048L*512), 256>>>(Whh_f, 512, 2048, 512,
                                          BF + BO_WHF, WH_LOSZ, 2048L*512);
    split_bf16<<<sgrid(2048L*512), 256>>>(Whh_b, 512, 2048, 512,
                                          BF + BO_WHB, WH_LOSZ, 2048L*512);
    split_bf16<<<sgrid(2048L*512), 256>>>(Whh_d, 512, 2048, 512,
                                          BF + BO_WHD, WH_LOSZ, 2048L*512);
    split_bf16<<<sgrid(2560L*2048), 256>>>(feats, 2048, 2560, 2048,
                                           BF + BO_FEATS, 2560L*2048, 2560L*2048);

    // x = feats @ feat_W^T + feat_b  -> written DIRECTLY as bf16 hi/lo split
    gemm_mma<<<dim3(20, 4), 256, MMA_SMEM>>>(BF + BO_FEATS, 2560L*2048, BF + BO_FW, 512L*2048,
                                             nullptr, CH, 2560, CH, CDF, feat_b, nullptr,
                                             BF + BO_X, 2560L*512);

    // encoder input-gate precompute
    gemm_mma<<<dim3(20, 16), 256, MMA_SMEM>>>(BF + BO_X, 2560L*512, BF + BO_WIF, 2048L*512,
                                              ginF, G4, 2560, G4, CH, bih_f, bhh_f, nullptr, 0);
    gemm_mma<<<dim3(20, 16), 256, MMA_SMEM>>>(BF + BO_X, 2560L*512, BF + BO_WIB, 2048L*512,
                                              ginB, G4, 2560, G4, CH, bih_b, bhh_b, nullptr, 0);

    // fused fwd+bwd encoder LSTMs (HMMA step GEMM)
    enc_lstm2<<<128, 256>>>(BF + BO_WHF, BF + BO_WHB, ginF, ginB,
                            hF, hB, BF + BO_HFS, BF + BO_HBS, BF + BO_HZS,
                            cF, cBb, part, partB);

    // ctx[b] = sum_l enc[b,l,:]  (attention collapses: softmax over singleton axis)
    ctx_sum<<<256, 256>>>(hF, hB, ctx);

    // decoder input-gate precompute
    gather_emb_split<<<(CT * CB * CE) / 256, 256>>>(emb, targets, BF + BO_DEMB, 2560L*512);
    gemm_mma<<<dim3(20, 16), 256, MMA_SMEM>>>(BF + BO_DEMB, 2560L*512, BF + BO_WID, 2048L*512,
                                              embW, G4, 2496, G4, CE, nullptr, nullptr,
                                              nullptr, 0);
    gemm_small64<<<dim3(64, 4), 256>>>(ctx, 2 * CH, Wih_d + CE, 2 * CH + CE, part, G4, 256);
    ctx_combine<<<512, 256>>>(part, bih_d, bhh_d, ctxW);

    // decoder LSTM persistent (h kept ONLY as bf16 split in BO_HD, [B][T][H] layout)
    lstm_persist<<<128, 256>>>(BF + BO_WHD, embW, (long)CB * G4, G4, ctxW,
                               BF + BO_HZS, BF + BO_HD, 2560L*512, CT * CH,
                               cD, part, CT);

    // output projection: out[b,t,:] = hD[b,t,:] @ out_W^T + out_b  (HMMA)
    gemm_mma<<<dim3(20, 157), 256, MMA_SMEM>>>(BF + BO_HD, 2560L*512, BF + BO_WOUT, 20096L*512,
                                               out, CV, 2496, CV, CH, out_b, nullptr,
                                               nullptr, 0);
}

// round 17
// speedup vs baseline: 1.9859x; 1.0140x over previous
#include <cuda_runtime.h>
#include <cuda_bf16.h>
#include <math.h>
#include <stdint.h>

// Problem dims
#define CB   64      // batch
#define CL   40      // seq len
#define CT   39      // decoder steps (L-1)
#define CH   512     // hidden
#define CDF  2048    // feature dim
#define CE   512     // embedding dim
#define CV   20000   // vocab
#define G4   2048    // 4*H

typedef unsigned long long u64;

// ---------------- fp32 scratch ----------------
constexpr int OFF_X    = 0;
constexpr int OFF_GINF = OFF_X    + CB*CL*CH;
constexpr int OFF_GINB = OFF_GINF + CB*CL*G4;
constexpr int OFF_HF   = OFF_GINB + CB*CL*G4;
constexpr int OFF_HB   = OFF_HF   + CL*CB*CH;
constexpr int OFF_HD   = OFF_HB   + CL*CB*CH;     // (fp32 hD retained but unused)
constexpr int OFF_CF   = OFF_HD   + CB*CT*CH;
constexpr int OFF_CB2  = OFF_CF   + CB*CH;
constexpr int OFF_CD   = OFF_CB2  + CB*CH;
constexpr int OFF_HZ   = OFF_CD   + CB*CH;
constexpr int OFF_CTX  = OFF_HZ   + CB*CH;
constexpr int OFF_DEMB = OFF_CTX  + CB*2*CH;
constexpr int OFF_EMBW = OFF_DEMB + CT*CB*CE;
constexpr int OFF_CTXW = OFF_EMBW + CT*CB*G4;
constexpr int OFF_PART = OFF_CTXW + CB*G4;
constexpr int SCRATCH_TOTAL = OFF_PART + 16*CB*G4;   // part: 8 slices x2 directions
__device__ __align__(256) float g_scratch[SCRATCH_TOTAL];
__device__ unsigned g_bar = 0;   // atomic barrier counter (always 0 between launches)

// ---------------- bf16 hi/lo scratch (hi at off, lo at off + PLANE size) ----------
constexpr long BO_WOUT  = 0;                               // 20096 x 512 (pad of 20000)
constexpr long BO_FW    = BO_WOUT  + 2L*20096*512;         // 512 x 2048
constexpr long BO_WIF   = BO_FW    + 2L*512*2048;          // 2048 x 512
constexpr long BO_WIB   = BO_WIF   + 2L*2048*512;
constexpr long BO_WID   = BO_WIB   + 2L*2048*512;          // 2048 x 512 (first E cols)
constexpr long BO_FEATS = BO_WID   + 2L*2048*512;          // 2560 x 2048
constexpr long BO_X     = BO_FEATS + 2L*2560*2048;         // 2560 x 512
constexpr long BO_DEMB  = BO_X     + 2L*2560*512;          // 2560 x 512 (pad of 2496)
constexpr long BO_HD    = BO_DEMB  + 2L*2560*512;          // 2560 x 512 (pad of 2496)
constexpr long BO_WHF   = BO_HD    + 2L*2560*512;          // 2048 x 512 (Whh_f split)
constexpr long BO_WHB   = BO_WHF   + 2L*2048*512;
constexpr long BO_WHD   = BO_WHB   + 2L*2048*512;
constexpr long BO_HFS   = BO_WHD   + 2L*2048*512;          // [CL][CB][CH] h split fwd
constexpr long BO_HBS   = BO_HFS   + 2L*CL*CB*CH;
constexpr long BO_HZS   = BO_HBS   + 2L*CL*CB*CH;          // zero h split (64x512)
constexpr long BF_TOTAL = BO_HZS   + 2L*CB*CH;
__device__ __align__(256) __nv_bfloat16 g_bf[BF_TOTAL];

// lo-plane offset (ELEMENT count of ONE plane) for the Whh splits.
constexpr long WH_LOSZ = 2048L * 512;

// ---------------- helpers ----------------
__device__ __forceinline__ void fma2(u64 &d, u64 a, u64 b) {
    asm("fma.rn.f32x2 %0, %1, %2, %0;" : "+l"(d) : "l"(a), "l"(b));
}
__device__ __forceinline__ float pairsum(u64 v) {
    float lo = __uint_as_float((unsigned)(v & 0xffffffffull));
    float hi = __uint_as_float((unsigned)(v >> 32));
    return lo + hi;
}
__device__ __forceinline__ void sts4(float* dst, float4 v) {
    *reinterpret_cast<float2*>(dst)     = make_float2(v.x, v.y);
    *reinterpret_cast<float2*>(dst + 2) = make_float2(v.z, v.w);
}
__device__ __forceinline__ uint32_t smem_u32(const void* p) {
    uint32_t a;
    asm("{ .reg .u64 t; cvta.to.shared.u64 t, %1; cvt.u32.u64 %0, t; }" : "=r"(a) : "l"(p));
    return a;
}
__device__ __forceinline__ void cp16(uint32_t dst, const void* src) {
    asm volatile("cp.async.cg.shared.global [%0], [%1], 16;" :: "r"(dst), "l"(src) : "memory");
}
__device__ __forceinline__ void cp_commit() {
    asm volatile("cp.async.commit_group;" ::: "memory");
}
__device__ __forceinline__ void cp_wait0() {
    asm volatile("cp.async.wait_group 0;" ::: "memory");
}
__device__ __forceinline__ void cp_wait1() {
    asm volatile("cp.async.wait_group 1;" ::: "memory");
}
__device__ __forceinline__ void ldsm4(uint32_t* r, uint32_t addr) {
    asm volatile("ldmatrix.sync.aligned.m8n8.x4.shared.b16 {%0,%1,%2,%3}, [%4];"
                 : "=r"(r[0]), "=r"(r[1]), "=r"(r[2]), "=r"(r[3]) : "r"(addr));
}
__device__ __forceinline__ void mma16816(float* d, const uint32_t* a, const uint32_t* b) {
    asm volatile("mma.sync.aligned.m16n8k16.row.col.f32.bf16.bf16.f32 "
                 "{%0,%1,%2,%3}, {%4,%5,%6,%7}, {%8,%9}, {%0,%1,%2,%3};"
                 : "+f"(d[0]), "+f"(d[1]), "+f"(d[2]), "+f"(d[3])
                 : "r"(a[0]), "r"(a[1]), "r"(a[2]), "r"(a[3]), "r"(b[0]), "r"(b[1]));
}
// swizzled element index for (row r, k-chunk c) in a [128][32] bf16 tile; 8 elems/chunk.
__device__ __forceinline__ int swzi(int r, int c) {
    int cc = (c + r + (r >> 2)) & 3;
    return r * 32 + cc * 8;
}
// BYTE offset for (row r, 16B-chunk c8) in a [rows][64] bf16 tile (128B rows, XOR swizzle)
__device__ __forceinline__ uint32_t sw64(int r, int c8) {
    return (uint32_t)((r << 7) + (((c8 ^ (r & 7)) & 7) << 4));
}
__device__ __forceinline__ void split1(float v, __nv_bfloat16& h, __nv_bfloat16& l) {
    h = __float2bfloat16(v);
    l = __float2bfloat16(v - __bfloat162float(h));
}

// ---------------- atomic-counter grid barrier (128 resident blocks) ----------------
__device__ __forceinline__ void grid_bar(unsigned &target) {
    __syncthreads();
    target += 128u;
    if (threadIdx.x == 0) {
        __threadfence();                       // release
        atomicAdd(&g_bar, 1u);
        unsigned v;
        do {
            asm volatile("ld.volatile.global.u32 %0, [%1];" : "=r"(v) : "l"(&g_bar));
        } while (v < target);
        __threadfence();                       // acquire
    }
    __syncthreads();
}
__device__ __forceinline__ void grid_bar_final(unsigned target) {
    __syncthreads();
    if (threadIdx.x == 0) {
        __threadfence();
        unsigned old = atomicAdd(&g_bar, 1u);
        if (old == target + 127u) {            // last arriver resets for next launch
            __threadfence();
            asm volatile("st.volatile.global.u32 [%0], %1;" :: "l"(&g_bar), "r"(0u));
        }
    }
}

// ================= split fp32 -> bf16 hi/lo (with row padding to zeros) ============
__global__ void split_bf16(const float* __restrict__ src, int ld, int rows_valid, int cols,
                           __nv_bfloat16* __restrict__ hi, long losz, long total)
{
    long idx = (long)blockIdx.x * 256 + threadIdx.x;
    if (idx >= total) return;
    long r = idx / cols;
    int  c = (int)(idx - r * cols);
    float v = (r < rows_valid) ? src[r * (long)ld + c] : 0.f;
    __nv_bfloat16 h, l; split1(v, h, l);
    hi[idx]        = h;
    hi[idx + losz] = l;
}

// ================= HMMA GEMM (double-buffered, occ-2): C = A * W^T (+b0+b1) ========
constexpr int MMA_STAGE_B = 32768;
constexpr int MMA_SMEM    = 2 * MMA_STAGE_B;

__global__ __launch_bounds__(256, 2) void gemm_mma(
    const __nv_bfloat16* __restrict__ Ah, long Asz,
    const __nv_bfloat16* __restrict__ Wh, long Wsz,
    float* __restrict__ C, int ldc, int Mvalid, int N, int K,
    const float* __restrict__ bias0, const float* __restrict__ bias1,
    __nv_bfloat16* __restrict__ Csp, long Csp_losz)
{
    extern __shared__ __align__(128) __nv_bfloat16 dynsmem[];
    const uint32_t base = smem_u32(dynsmem);

    const int tid  = threadIdx.x;
    const int wid  = tid >> 5, lane = tid & 31;
    const int wm   = wid >> 2;
    const int wn   = wid & 3;
    const int m0   = blockIdx.x * 128, n0 = blockIdx.y * 128;

    const __nv_bfloat16* Al = Ah + Asz;
    const __nv_bfloat16* Wl = Wh + Wsz;

    float acc[4][4][4];
#pragma unroll
    for (int i = 0; i < 4; i++)
#pragma unroll
        for (int j = 0; j < 4; j++)
#pragma unroll
            for (int q = 0; q < 4; q++) acc[i][j][q] = 0.f;

    const int s_r0 = tid >> 2, s_c0 = tid & 3;
    const int s_r1 = (tid + 256) >> 2, s_c1 = tid & 3;
    const uint32_t so0 = (uint32_t)swzi(s_r0, s_c0) * 2;
    const uint32_t so1 = (uint32_t)swzi(s_r1, s_c1) * 2;

    const int a_r  = lane & 15;
    const int a_cg = lane >> 4;
    const int b_r  = (lane & 7) + ((lane >> 4) << 3);
    const int b_cg = (lane >> 3) & 1;

    const int nch = K >> 5;

    auto load_stage = [&](int c, uint32_t sb) {
        const int k0 = c << 5;
        long ga0 = (long)(m0 + s_r0) * K + k0 + s_c0 * 8;
        long gb0 = (long)(n0 + s_r0) * K + k0 + s_c0 * 8;
        cp16(sb +         so0, Ah + ga0);
        cp16(sb +  8192 + so0, Al + ga0);
        cp16(sb + 16384 + so0, Wh + gb0);
        cp16(sb + 24576 + so0, Wl + gb0);
        long ga1 = (long)(m0 + s_r1) * K + k0 + s_c1 * 8;
        long gb1 = (long)(n0 + s_r1) * K + k0 + s_c1 * 8;
        cp16(sb +         so1, Ah + ga1);
        cp16(sb +  8192 + so1, Al + ga1);
        cp16(sb + 16384 + so1, Wh + gb1);
        cp16(sb + 24576 + so1, Wl + gb1);
        cp_commit();
    };

    load_stage(0, base);

    for (int c = 0; c < nch; c++) {
        const uint32_t cb = base + (uint32_t)(c & 1) * MMA_STAGE_B;
        if (c + 1 < nch) {
            load_stage(c + 1, base + (uint32_t)((c + 1) & 1) * MMA_STAGE_B);
            cp_wait1();
        } else {
            cp_wait0();
        }
        __syncthreads();

        const uint32_t bAh = cb, bAl = cb + 8192, bWh = cb + 16384, bWl = cb + 24576;
        // Restructured for lower register pressure: B-fragments once per k16,
        // then per-t A-fragments + immediate mma issue.
#pragma unroll
        for (int h = 0; h < 2; h++) {
            uint32_t bh[4][2], bl[4][2];
#pragma unroll
            for (int p = 0; p < 2; p++) {
                int r  = wn * 32 + p * 16 + b_r;
                int ch = 2 * h + b_cg;
                uint32_t off = (uint32_t)swzi(r, ch) * 2;
                uint32_t tmp[4];
                ldsm4(tmp, bWh + off);
                bh[2*p][0] = tmp[0]; bh[2*p][1] = tmp[1];
                bh[2*p+1][0] = tmp[2]; bh[2*p+1][1] = tmp[3];
                ldsm4(tmp, bWl + off);
                bl[2*p][0] = tmp[0]; bl[2*p][1] = tmp[1];
                bl[2*p+1][0] = tmp[2]; bl[2*p+1][1] = tmp[3];
            }
#pragma unroll
            for (int t = 0; t < 4; t++) {
                uint32_t ah[4], al[4];
                int r  = wm * 64 + t * 16 + a_r;
                int ch = 2 * h + a_cg;
                uint32_t off = (uint32_t)swzi(r, ch) * 2;
                ldsm4(ah, bAh + off);
                ldsm4(al, bAl + off);
#pragma unroll
                for (int n = 0; n < 4; n++) {
                    mma16816(acc[t][n], ah, bh[n]);
                    mma16816(acc[t][n], ah, bl[n]);
                    mma16816(acc[t][n], al, bh[n]);
                }
            }
        }
        __syncthreads();
    }

#pragma unroll
    for (int t = 0; t < 4; t++) {
#pragma unroll
        for (int n = 0; n < 4; n++) {
            int row = m0 + wm * 64 + t * 16 + (lane >> 2);
            int col = n0 + wn * 32 + n * 8 + 2 * (lane & 3);
            if (col < N) {
                float bx = 0.f, by = 0.f;
                if (bias0) { bx += bias0[col]; by += bias0[col + 1]; }
                if (bias1) { bx += bias1[col]; by += bias1[col + 1]; }
#pragma unroll
                for (int half = 0; half < 2; half++) {
                    int r = row + 8 * half;
                    if (r < Mvalid) {
                        float vx = acc[t][n][2*half]     + bx;
                        float vy = acc[t][n][2*half + 1] + by;
                        if (C)
                            *reinterpret_cast<float2*>(C + (long)r * ldc + col) =
                                make_float2(vx, vy);
                        if (Csp) {
                            __nv_bfloat16 hx, lx, hy, ly;
                            split1(vx, hx, lx); split1(vy, hy, ly);
                            long o = (long)r * ldc + col;
                            Csp[o] = hx; Csp[o + 1] = hy;
                            Csp[o + Csp_losz] = lx; Csp[o + Csp_losz + 1] = ly;
                        }
                    }
                }
            }
        }
    }
}

// ---------------- small-M GEMM (used once for ctx @ Wih_d[:,E:]) ----------------
__global__ __launch_bounds__(256) void gemm_small64(
    const float* __restrict__ A, int lda,
    const float* __restrict__ W, int ldw,
    float* __restrict__ P, int N, int Kps)
{
    __shared__ float As[64][34];
    __shared__ float Ws[32][34];
    const int tid  = threadIdx.x;
    const int n0   = blockIdx.x * 32;
    const int kb   = blockIdx.y * Kps;
    const int tm   = tid >> 4;
    const int tn   = tid & 15;
    const int lrow = tid >> 3;
    const int lcol = (tid & 7) << 2;

    u64 acc[4][2];
#pragma unroll
    for (int i = 0; i < 4; i++) { acc[i][0] = 0ull; acc[i][1] = 0ull; }

    const int nk = Kps >> 5;
    float4 pa0, pa1, pw;
    {
        int k = kb + lcol;
        pa0 = *reinterpret_cast<const float4*>(A + (long)lrow * lda + k);
        pa1 = *reinterpret_cast<const float4*>(A + (long)(lrow + 32) * lda + k);
        pw  = *reinterpret_cast<const float4*>(W + (long)(n0 + lrow) * ldw + k);
    }
    for (int c = 0; c < nk; c++) {
        sts4(&As[lrow][lcol],      pa0);
        sts4(&As[lrow + 32][lcol], pa1);
        sts4(&Ws[lrow][lcol],      pw);
        __syncthreads();
        if (c + 1 < nk) {
            int k = kb + ((c + 1) << 5) + lcol;
            pa0 = *reinterpret_cast<const float4*>(A + (long)lrow * lda + k);
            pa1 = *reinterpret_cast<const float4*>(A + (long)(lrow + 32) * lda + k);
            pw  = *reinterpret_cast<const float4*>(W + (long)(n0 + lrow) * ldw + k);
        }
#pragma unroll
        for (int kk = 0; kk < 16; kk++) {
            u64 a2[4], w2[2];
#pragma unroll
            for (int i = 0; i < 4; i++)
                a2[i] = *reinterpret_cast<const u64*>(&As[tm + 16 * i][kk << 1]);
#pragma unroll
            for (int j = 0; j < 2; j++)
                w2[j] = *reinterpret_cast<const u64*>(&Ws[tn + 16 * j][kk << 1]);
#pragma unroll
            for (int i = 0; i < 4; i++)
#pragma unroll
                for (int j = 0; j < 2; j++) fma2(acc[i][j], a2[i], w2[j]);
        }
        __syncthreads();
    }
    float* out = P + (long)blockIdx.y * 64 * N;
#pragma unroll
    for (int i = 0; i < 4; i++)
#pragma unroll
        for (int j = 0; j < 2; j++)
            out[(tm + 16 * i) * (long)N + n0 + tn + 16 * j] = pairsum(acc[i][j]);
}

// ---------------- persistent LSTM machinery (HMMA step GEMM) ----------------
__device__ __forceinline__ void step_gemm_mma(
    const __nv_bfloat16* __restrict__ Ah, long Alosz, int lda,
    const __nv_bfloat16* __restrict__ Wh, long Wlosz,
    float* __restrict__ part, int bx,
    uint32_t bAh, uint32_t bAl, uint32_t bBh, uint32_t bBl)
{
    const int tid  = threadIdx.x;
    const int wid  = tid >> 5, lane = tid & 31;
    const int wm   = wid >> 2;        // 0..1 (32 rows each)
    const int wn   = wid & 3;         // 0..3 (32 cols each)
    const int kz   = bx >> 4;         // 0..7
    const int nb   = bx & 15;         // 0..15
    const int k0   = kz << 6;
    const int n0   = nb << 7;

    const __nv_bfloat16* Al_ = Ah + Alosz;
    const __nv_bfloat16* Wl_ = Wh + Wlosz;

#pragma unroll
    for (int u = tid; u < 512; u += 256) {         // A: 64 rows x 8 chunks
        int r = u >> 3, c = u & 7;
        uint32_t so = sw64(r, c);
        long g = (long)r * lda + k0 + c * 8;
        cp16(bAh + so, Ah  + g);
        cp16(bAl + so, Al_ + g);
    }
#pragma unroll
    for (int u = tid; u < 1024; u += 256) {        // B: 128 rows x 8 chunks
        int r = u >> 3, c = u & 7;
        uint32_t so = sw64(r, c);
        long g = (long)(n0 + r) * CH + k0 + c * 8;
        cp16(bBh + so, Wh  + g);
        cp16(bBl + so, Wl_ + g);
    }
    cp_commit(); cp_wait0();
    __syncthreads();

    float acc[2][4][4];
#pragma unroll
    for (int i = 0; i < 2; i++)
#pragma unroll
        for (int j = 0; j < 4; j++)
#pragma unroll
            for (int q = 0; q < 4; q++) acc[i][j][q] = 0.f;

    const int a_r  = lane & 15;
    const int a_cg = lane >> 4;
    const int b_r  = (lane & 7) + ((lane >> 4) << 3);
    const int b_cg = (lane >> 3) & 1;

#pragma unroll
    for (int h = 0; h < 4; h++) {                  // 4 k16 steps (K=64)
        uint32_t bh[4][2], bl[4][2];
#pragma unroll
        for (int p = 0; p < 2; p++) {
            int r  = wn * 32 + p * 16 + b_r;
            int ch = 2 * h + b_cg;
            uint32_t tmp[4];
            ldsm4(tmp, bBh + sw64(r, ch));
            bh[2*p][0] = tmp[0]; bh[2*p][1] = tmp[1];
            bh[2*p+1][0] = tmp[2]; bh[2*p+1][1] = tmp[3];
            ldsm4(tmp, bBl + sw64(r, ch));
            bl[2*p][0] = tmp[0]; bl[2*p][1] = tmp[1];
            bl[2*p+1][0] = tmp[2]; bl[2*p+1][1] = tmp[3];
        }
#pragma unroll
        for (int t = 0; t < 2; t++) {
            uint32_t ah[4], al[4];
            int r  = wm * 32 + t * 16 + a_r;
            int ch = 2 * h + a_cg;
            ldsm4(ah, bAh + sw64(r, ch));
            ldsm4(al, bAl + sw64(r, ch));
#pragma unroll
            for (int n = 0; n < 4; n++) {
                mma16816(acc[t][n], ah, bh[n]);
                mma16816(acc[t][n], ah, bl[n]);
                mma16816(acc[t][n], al, bh[n]);
            }
        }
    }

    float* outp = part + (long)kz * (CB * G4);
#pragma unroll
    for (int t = 0; t < 2; t++)
#pragma unroll
        for (int n = 0; n < 4; n++) {
            int row = wm * 32 + t * 16 + (lane >> 2);
            int col = n0 + wn * 32 + n * 8 + 2 * (lane & 3);
            *reinterpret_cast<float2*>(outp + (long)row * G4 + col) =
                make_float2(acc[t][n][0], acc[t][n][1]);
            *reinterpret_cast<float2*>(outp + (long)(row + 8) * G4 + col) =
                make_float2(acc[t][n][2], acc[t][n][3]);
        }
}

// gates: G = sum_z part[z] + D1 (+D2); update c; write h (fp32 optional) + bf16 split
__device__ __forceinline__ void gates_fn(const float* P, const float* D1, int ldd1,
                                         const float* D2, float* c,
                                         float* h_out, int h_ld, int idx,
                                         __nv_bfloat16* hs, long hs_losz)
{
    int b = idx >> 9, u = idx & 511;
    const float* d1 = D1 + (long)b * ldd1;
    float gi = d1[u], gf = d1[512 + u], gg = d1[1024 + u], go = d1[1536 + u];
#pragma unroll
    for (int z = 0; z < 8; z++) {
        const float* gz = P + (long)z * (CB * G4) + (long)b * G4;
        gi += gz[u]; gf += gz[512 + u]; gg += gz[1024 + u]; go += gz[1536 + u];
    }
    if (D2) {
        const float* d2 = D2 + (long)b * G4;
        gi += d2[u]; gf += d2[512 + u]; gg += d2[1024 + u]; go += d2[1536 + u];
    }
    float i_ = 1.f / (1.f + expf(-gi));
    float f_ = 1.f / (1.f + expf(-gf));
    float g_ = tanhf(gg);
    float o_ = 1.f / (1.f + expf(-go));
    float cn = f_ * c[idx] + i_ * g_;
    c[idx] = cn;
    float hv = o_ * tanhf(cn);
    long lin = (long)b * h_ld + u;
    if (h_out) h_out[lin] = hv;
    __nv_bfloat16 hh, hl; split1(hv, hh, hl);
    hs[lin] = hh;
    hs[lin + hs_losz] = hl;
}

// ---- fused fwd+bwd encoder LSTMs: interleaved phases, one barrier per phase ----
__global__ __launch_bounds__(256) void enc_lstm2(
    const __nv_bfloat16* __restrict__ whfS, const __nv_bfloat16* __restrict__ whbS,
    const float* __restrict__ ginF,  const float* __restrict__ ginB,
    float* __restrict__ hF, float* __restrict__ hB,
    __nv_bfloat16* __restrict__ hFs, __nv_bfloat16* __restrict__ hBs,
    const __nv_bfloat16* __restrict__ hzs,
    float* __restrict__ cF, float* __restrict__ cB2,
    float* __restrict__ partF, float* __restrict__ partB)
{
    __shared__ __align__(128) __nv_bfloat16 sA[2][64 * 64];
    __shared__ __align__(128) __nv_bfloat16 sB[2][128 * 64];
    const uint32_t bAh = smem_u32(sA[0]), bAl = smem_u32(sA[1]);
    const uint32_t bBh = smem_u32(sB[0]), bBl = smem_u32(sB[1]);
    constexpr long HS_LOSZ = (long)CL * CB * CH;
    constexpr long HZ_LOSZ = (long)CB * CH;

    unsigned target = 0;
    const int bx  = blockIdx.x;
    const int idx = bx * 256 + threadIdx.x;
    for (int p = 0; p < 2 * CL; p++) {
        const int li = p & 1;            // 0 = fwd, 1 = bwd
        const int s  = p >> 1;
        const __nv_bfloat16* whS = li ? whbS : whfS;
        const float* gin  = li ? ginB  : ginF;
        float* hbase = li ? hB : hF;
        __nv_bfloat16* hsb = li ? hBs : hFs;
        float* cc    = li ? cB2 : cF;
        float* part  = li ? partB : partF;
        const int l = li ? (CL - 1 - s) : s;
        const __nv_bfloat16* hin; long hlosz;
        if (s == 0) { hin = hzs; hlosz = HZ_LOSZ; }
        else {
            int lp = li ? (l + 1) : (l - 1);
            hin = hsb + (long)lp * CB * CH; hlosz = HS_LOSZ;
        }
        step_gemm_mma(hin, hlosz, CH, whS, WH_LOSZ, part, bx,
                      bAh, bAl, bBh, bBl);
        grid_bar(target);                 // part(li,s) complete across all blocks
        gates_fn(part, gin + (long)l * G4, CL * G4, nullptr, cc,
                 hbase + (long)l * CB * CH, CH, idx,
                 hsb + (long)l * CB * CH, HS_LOSZ);
        // h(li,s) consumed by gemm(li,s+1) two phases later -> guarded by next grid_bar
    }
    grid_bar_final(target);
}

// ---- decoder persistent LSTM (2 barriers per step; bf16-split h in/out) ----
__global__ __launch_bounds__(256) void lstm_persist(
    const __nv_bfloat16* __restrict__ whS,
    const float* __restrict__ gin, long gin_step, int gin_ld,
    const float* __restrict__ D2,
    const __nv_bfloat16* __restrict__ hzs,
    __nv_bfloat16* __restrict__ hs, long hs_losz, int h_ld,
    float* __restrict__ c, float* __restrict__ part, int nsteps)
{
    __shared__ __align__(128) __nv_bfloat16 sA[2][64 * 64];
    __shared__ __align__(128) __nv_bfloat16 sB[2][128 * 64];
    const uint32_t bAh = smem_u32(sA[0]), bAl = smem_u32(sA[1]);
    const uint32_t bBh = smem_u32(sB[0]), bBl = smem_u32(sB[1]);

    unsigned target = 0;
    const int bx  = blockIdx.x;
    const int idx = bx * 256 + threadIdx.x;
    for (int s = 0; s < nsteps; s++) {
        const __nv_bfloat16* hin;
        long hlosz; int hlda;
        if (s == 0) { hin = hzs; hlosz = (long)CB * CH; hlda = CH; }
        else        { hin = hs + (long)(s - 1) * CH; hlosz = hs_losz; hlda = h_ld; }
        step_gemm_mma(hin, hlosz, hlda, whS, WH_LOSZ, part, bx,
                      bAh, bAl, bBh, bBl);
        grid_bar(target);
        gates_fn(part, gin + (long)s * gin_step, gin_ld, D2, c,
                 nullptr, h_ld, idx, hs + (long)s * CH, hs_losz);
        if (s + 1 < nsteps) grid_bar(target);
        else                grid_bar_final(target);
    }
}

// ---------------- small elementwise kernels ----------------
__global__ void zero_state(float* cF, float* cB, float* cD, float* hz)
{
    int idx = blockIdx.x * blockDim.x + threadIdx.x;
    cF[idx] = 0.f; cB[idx] = 0.f; cD[idx] = 0.f; hz[idx] = 0.f;
}

// zero pad rows of DEMB/HD splits + the hz bf16 split
__global__ void zero_bf_pads(__nv_bfloat16* base)
{
    int i = blockIdx.x * 256 + threadIdx.x;   // 0..32767
    long r = 2496L * 512 + i;
    __nv_bfloat16 z = __float2bfloat16(0.f);
    base[BO_DEMB + r] = z;
    base[BO_DEMB + 2560L * 512 + r] = z;
    base[BO_HD + r] = z;
    base[BO_HD + 2560L * 512 + r] = z;
    base[BO_HZS + i] = z;
    base[BO_HZS + 32768 + i] = z;
}

__global__ void ctx_sum(const float* __restrict__ hF, const float* __restrict__ hB,
                        float* __restrict__ ctx)
{
    int idx = blockIdx.x * blockDim.x + threadIdx.x;  // 64*1024
    int b = idx >> 10, j = idx & 1023;
    float s = 0.f;
    if (j < 512) {
        for (int l = 0; l < CL; l++) s += hF[((long)l * CB + b) * CH + j];
    } else {
        int j2 = j - 512;
        for (int l = 0; l < CL; l++) s += hB[((long)l * CB + b) * CH + j2];
    }
    ctx[idx] = s;
}

__global__ void ctx_combine(const float* __restrict__ P,
                            const float* __restrict__ b0,
                            const float* __restrict__ b1,
                            float* __restrict__ ctxW)
{
    int idx = blockIdx.x * blockDim.x + threadIdx.x;  // 64*2048
    int b = idx >> 11, n = idx & 2047;
    float s = b0[n] + b1[n];
#pragma unroll
    for (int z = 0; z < 4; z++) s += P[((long)z * CB + b) * G4 + n];
    ctxW[idx] = s;
}

__global__ void gather_emb_split(const float* __restrict__ emb, const int* __restrict__ targets,
                                 __nv_bfloat16* __restrict__ dst, long losz)
{
    int idx = blockIdx.x * blockDim.x + threadIdx.x;  // 39*64*512
    int e = idx & 511;
    int r = idx >> 9;
    int t = r / CB, b = r - t * CB;
    int tgt = targets[b * CL + t];
    float v = emb[(long)tgt * CE + e];
    __nv_bfloat16 h, l; split1(v, h, l);
    dst[idx] = h;
    dst[idx + losz] = l;
}

// ---------------- launch ----------------
static inline int sgrid(long n) { return (int)((n + 255) / 256); }

extern "C" void kernel_launch(void* const* d_in, const int* in_sizes, int n_in,
                              void* d_out, int out_size)
{
    (void)in_sizes; (void)n_in; (void)out_size;
    const float* feats  = (const float*)d_in[0];
    const float* feat_W = (const float*)d_in[1];
    const float* feat_b = (const float*)d_in[2];
    const float* Wih_f  = (const float*)d_in[3];
    const float* Whh_f  = (const float*)d_in[4];
    const float* bih_f  = (const float*)d_in[5];
    const float* bhh_f  = (const float*)d_in[6];
    const float* Wih_b  = (const float*)d_in[7];
    const float* Whh_b  = (const float*)d_in[8];
    const float* bih_b  = (const float*)d_in[9];
    const float* bhh_b  = (const float*)d_in[10];
    const float* emb    = (const float*)d_in[11];
    const float* Wih_d  = (const float*)d_in[12];
    const float* Whh_d  = (const float*)d_in[13];
    const float* bih_d  = (const float*)d_in[14];
    const float* bhh_d  = (const float*)d_in[15];
    // d_in[16..20]: attention params — provably unused (softmax over singleton axis -> ones)
    const float* out_W  = (const float*)d_in[21];
    const float* out_b  = (const float*)d_in[22];
    const int*   targets = (const int*)d_in[23];
    float* out = (float*)d_out;

    float* S = nullptr;
    cudaGetSymbolAddress((void**)&S, g_scratch);
    __nv_bfloat16* BF = nullptr;
    cudaGetSymbolAddress((void**)&BF, g_bf);

    float* ginF  = S + OFF_GINF;
    float* ginB  = S + OFF_GINB;
    float* hF    = S + OFF_HF;
    float* hB    = S + OFF_HB;
    float* cF    = S + OFF_CF;
    float* cBb   = S + OFF_CB2;
    float* cD    = S + OFF_CD;
    float* hz    = S + OFF_HZ;
    float* ctx   = S + OFF_CTX;
    float* embW  = S + OFF_EMBW;
    float* ctxW  = S + OFF_CTXW;
    float* part  = S + OFF_PART;                 // partF = part, partB = part + 8*CB*G4
    float* partB = part + 8L * CB * G4;

    cudaFuncSetAttribute(gemm_mma, cudaFuncAttributeMaxDynamicSharedMemorySize, MMA_SMEM);

    // Launch order puts the first gemm_mma at slot 6 so ncu (-s 5 -c 1) captures it.
    zero_state<<<128, 256>>>(cF, cBb, cD, hz);                               // 1
    zero_bf_pads<<<128, 256>>>(BF);                                          // 2
    split_bf16<<<sgrid(512L*2048), 256>>>(feat_W, 2048, 512, 2048,           // 3
                                          BF + BO_FW, 512L*2048, 512L*2048);
    split_bf16<<<sgrid(2560L*2048), 256>>>(feats, 2048, 2560, 2048,          // 4
                                           BF + BO_FEATS, 2560L*2048, 2560L*2048);
    split_bf16<<<sgrid(20096L*512), 256>>>(out_W, 512, 20000, 512,           // 5
                                           BF + BO_WOUT, 20096L*512, 20096L*512);
    // x = feats @ feat_W^T + feat_b  -> written DIRECTLY as bf16 hi/lo split
    gemm_mma<<<dim3(20, 4), 256, MMA_SMEM>>>(BF + BO_FEATS, 2560L*2048,      // 6 (profiled)
                                             BF + BO_FW, 512L*2048,
                                             nullptr, CH, 2560, CH, CDF, feat_b, nullptr,
                                             BF + BO_X, 2560L*512);

    split_bf16<<<sgrid(2048L*512), 256>>>(Wih_f, 512, 2048, 512,
                                          BF + BO_WIF, 2048L*512, 2048L*512);
    split_bf16<<<sgrid(2048L*512), 256>>>(Wih_b, 512, 2048, 512,
                                          BF + BO_WIB, 2048L*512, 2048L*512);
    split_bf16<<<sgrid(2048L*512), 256>>>(Wih_d, 2*CH + CE, 2048, 512,
                                          BF + BO_WID, 2048L*512, 2048L*512);
    split_bf16<<<sgrid(2048L*512), 256>>>(Whh_f, 512, 2048, 512,
                                          BF + BO_WHF, WH_LOSZ, 2048L*512);
    split_bf16<<<sgrid(2048L*512), 256>>>(Whh_b, 512, 2048, 512,
                                          BF + BO_WHB, WH_LOSZ, 2048L*512);
    split_bf16<<<sgrid(2048L*512), 256>>>(Whh_d, 512, 2048, 512,
                                          BF + BO_WHD, WH_LOSZ, 2048L*512);

    // encoder input-gate precompute
    gemm_mma<<<dim3(20, 16), 256, MMA_SMEM>>>(BF + BO_X, 2560L*512, BF + BO_WIF, 2048L*512,
                                              ginF, G4, 2560, G4, CH, bih_f, bhh_f, nullptr, 0);
    gemm_mma<<<dim3(20, 16), 256, MMA_SMEM>>>(BF + BO_X, 2560L*512, BF + BO_WIB, 2048L*512,
                                              ginB, G4, 2560, G4, CH, bih_b, bhh_b, nullptr, 0);

    // fused fwd+bwd encoder LSTMs (HMMA step GEMM)
    enc_lstm2<<<128, 256>>>(BF + BO_WHF, BF + BO_WHB, ginF, ginB,
                            hF, hB, BF + BO_HFS, BF + BO_HBS, BF + BO_HZS,
                            cF, cBb, part, partB);

    // ctx[b] = sum_l enc[b,l,:]  (attention collapses: softmax over singleton axis)
    ctx_sum<<<256, 256>>>(hF, hB, ctx);

    // decoder input-gate precompute
    gather_emb_split<<<(CT * CB * CE) / 256, 256>>>(emb, targets, BF + BO_DEMB, 2560L*512);
    gemm_mma<<<dim3(20, 16), 256, MMA_SMEM>>>(BF + BO_DEMB, 2560L*512, BF + BO_WID, 2048L*512,
                                              embW, G4, 2496, G4, CE, nullptr, nullptr,
                                              nullptr, 0);
    gemm_small64<<<dim3(64, 4), 256>>>(ctx, 2 * CH, Wih_d + CE, 2 * CH + CE, part, G4, 256);
    ctx_combine<<<512, 256>>>(part, bih_d, bhh_d, ctxW);

    // decoder LSTM persistent (h kept ONLY as bf16 split in BO_HD, [B][T][H] layout)
    lstm_persist<<<128, 256>>>(BF + BO_WHD, embW, (long)CB * G4, G4, ctxW,
                               BF + BO_HZS, BF + BO_HD, 2560L*512, CT * CH,
                               cD, part, CT);

    // output projection: out[b,t,:] = hD[b,t,:] @ out_W^T + out_b  (HMMA)
    gemm_mma<<<dim3(20, 157), 256, MMA_SMEM>>>(BF + BO_HD, 2560L*512, BF + BO_WOUT, 20096L*512,
                                               out, CV, 2496, CV, CH, out_b, nullptr,
                                               nullptr, 0);
}